// round 1
// baseline (speedup 1.0000x reference)
#include <cuda_runtime.h>
#include <cstdint>

// Problem constants
#define BATCH 8
#define SEQ   4
#define DMODEL 2048
#define NHEAD 32
#define HDIM  64
#define CACHE 4096
#define NKEY  (CACHE + SEQ)   // 4100
#define MROWS (BATCH * SEQ)   // 32

// ---------------- scratch (device globals; no allocation allowed) -------------
static __device__ float g_xq[MROWS * DMODEL];
static __device__ float g_xk[MROWS * DMODEL];
static __device__ float g_xv[MROWS * DMODEL];
static __device__ float g_attn[MROWS * DMODEL];
static __device__ float g_part[4][MROWS * DMODEL];

// ---------------- f32x2 helpers (Blackwell packed fp32 FMA) -------------------
__device__ __forceinline__ void ffma2(unsigned long long& d,
                                      unsigned long long a,
                                      unsigned long long b)
{
    asm volatile("fma.rn.f32x2 %0, %1, %2, %0;" : "+l"(d) : "l"(a), "l"(b));
}
__device__ __forceinline__ float2 unpack2(unsigned long long u)
{
    float2 r;
    asm volatile("mov.b64 {%0, %1}, %2;" : "=f"(r.x), "=f"(r.y) : "l"(u));
    return r;
}
union F4 { float4 v; unsigned long long u[2]; };

// ==============================================================================
// GEMM tile core: C[32, 64-tile] = X[32,2048] @ W[n,:]^T over K range.
// Thread layout: 256 threads, tx = lane (n in {tx, tx+32}), ty = warp (m in ty*4..+3).
// Accumulators are f32x2 packed over (k even, k odd); horizontal add at the end.
// Smem rows padded to 68 words: quarter-warp LDS.128 conflict-free.
// ==============================================================================
__device__ __forceinline__ void gemm_tile(
    const float* __restrict__ X, const float* __restrict__ W,
    float* __restrict__ out, int tile, int c_begin, int c_end,
    bool rope, const float* __restrict__ fc, const float* __restrict__ fs)
{
    __shared__ float Xs[32 * 68];
    __shared__ float Ws[64 * 68];

    const int tid = threadIdx.x;
    const int tx = tid & 31;
    const int ty = tid >> 5;

    unsigned long long acc[4][2];
#pragma unroll
    for (int i = 0; i < 4; i++) { acc[i][0] = 0ull; acc[i][1] = 0ull; }

    float4 px[2], pw[4];
    // prefetch first chunk into registers
    {
        const int k0 = c_begin * 64;
#pragma unroll
        for (int i = 0; i < 2; i++) {
            int fid = i * 256 + tid; int m = fid >> 4, c4 = fid & 15;
            px[i] = *(const float4*)(X + (size_t)m * DMODEL + k0 + c4 * 4);
        }
#pragma unroll
        for (int i = 0; i < 4; i++) {
            int fid = i * 256 + tid; int n = fid >> 4, c4 = fid & 15;
            pw[i] = *(const float4*)(W + (size_t)(tile * 64 + n) * DMODEL + k0 + c4 * 4);
        }
    }

    for (int c = c_begin; c < c_end; ++c) {
        // stage current chunk
#pragma unroll
        for (int i = 0; i < 2; i++) {
            int fid = i * 256 + tid; int m = fid >> 4, c4 = fid & 15;
            *(float4*)(Xs + m * 68 + c4 * 4) = px[i];
        }
#pragma unroll
        for (int i = 0; i < 4; i++) {
            int fid = i * 256 + tid; int n = fid >> 4, c4 = fid & 15;
            *(float4*)(Ws + n * 68 + c4 * 4) = pw[i];
        }
        __syncthreads();

        // prefetch next chunk (overlaps with compute below)
        if (c + 1 < c_end) {
            const int k0 = (c + 1) * 64;
#pragma unroll
            for (int i = 0; i < 2; i++) {
                int fid = i * 256 + tid; int m = fid >> 4, c4 = fid & 15;
                px[i] = *(const float4*)(X + (size_t)m * DMODEL + k0 + c4 * 4);
            }
#pragma unroll
            for (int i = 0; i < 4; i++) {
                int fid = i * 256 + tid; int n = fid >> 4, c4 = fid & 15;
                pw[i] = *(const float4*)(W + (size_t)(tile * 64 + n) * DMODEL + k0 + c4 * 4);
            }
        }

        // compute: 64 k per chunk, 8 at a time
#pragma unroll
        for (int kk = 0; kk < 64; kk += 8) {
            F4 w00, w01, w10, w11;
            w00.v = *(const float4*)(Ws + tx * 68 + kk);
            w01.v = *(const float4*)(Ws + tx * 68 + kk + 4);
            w10.v = *(const float4*)(Ws + (tx + 32) * 68 + kk);
            w11.v = *(const float4*)(Ws + (tx + 32) * 68 + kk + 4);
#pragma unroll
            for (int i = 0; i < 4; i++) {
                F4 xa, xb;
                xa.v = *(const float4*)(Xs + (ty * 4 + i) * 68 + kk);
                xb.v = *(const float4*)(Xs + (ty * 4 + i) * 68 + kk + 4);
                ffma2(acc[i][0], xa.u[0], w00.u[0]);
                ffma2(acc[i][0], xa.u[1], w00.u[1]);
                ffma2(acc[i][0], xb.u[0], w01.u[0]);
                ffma2(acc[i][0], xb.u[1], w01.u[1]);
                ffma2(acc[i][1], xa.u[0], w10.u[0]);
                ffma2(acc[i][1], xa.u[1], w10.u[1]);
                ffma2(acc[i][1], xb.u[0], w11.u[0]);
                ffma2(acc[i][1], xb.u[1], w11.u[1]);
            }
        }
        __syncthreads();
    }

    // epilogue (+ optional RoPE: pair (even,odd) n live in lanes (tx, tx^1))
#pragma unroll
    for (int i = 0; i < 4; i++) {
#pragma unroll
        for (int j = 0; j < 2; j++) {
            float2 h2 = unpack2(acc[i][j]);
            float val = h2.x + h2.y;
            const int nl = tx + j * 32;
            if (rope) {
                float partner = __shfl_xor_sync(0xffffffffu, val, 1);
                const int pidx = nl >> 1;               // hd pair index (tile aligned to head)
                const float cth = fc[i * (HDIM / 2) + pidx];  // s == i
                const float sth = fs[i * (HDIM / 2) + pidx];
                val = ((tx & 1) == 0) ? (val * cth - partner * sth)
                                      : (val * cth + partner * sth);
            }
            out[(size_t)(ty * 4 + i) * DMODEL + tile * 64 + nl] = val;
        }
    }
}

// ---------------- QKV projection + RoPE --------------------------------------
__global__ void __launch_bounds__(256) qkv_gemm_kernel(
    const float* __restrict__ x,
    const float* __restrict__ wq, const float* __restrict__ wk,
    const float* __restrict__ wv,
    const float* __restrict__ fc, const float* __restrict__ fs)
{
    const int g = blockIdx.x >> 5;     // 0=q, 1=k, 2=v
    const int tile = blockIdx.x & 31;
    const float* W = (g == 0) ? wq : (g == 1 ? wk : wv);
    float* out = (g == 0) ? g_xq : (g == 1 ? g_xk : g_xv);
    gemm_tile(x, W, out, tile, 0, 32, (g < 2), fc, fs);
}

// ---------------- output projection (split-K=4) ------------------------------
__global__ void __launch_bounds__(256) wo_gemm_kernel(const float* __restrict__ wo)
{
    const int ks = blockIdx.x >> 5;    // 0..3
    const int tile = blockIdx.x & 31;
    gemm_tile(g_attn, wo, g_part[ks], tile, ks * 8, ks * 8 + 8, false, nullptr, nullptr);
}

__global__ void __launch_bounds__(256) combine_kernel(float* __restrict__ out)
{
    const int i = blockIdx.x * 256 + threadIdx.x;
    out[i] = g_part[0][i] + g_part[1][i] + g_part[2][i] + g_part[3][i];
}

// ==============================================================================
// Attention: one block per (b, h). Scores (4 x 4100) held in smem.
//   Phase 1: stage 128 keys/chunk to smem, each thread computes 2 q-dots.
//   Phase 2: block softmax (4 rows x 64 threads).
//   Phase 3: AV — thread (q, d) streams cache_v coalesced, 16-deep unroll.
// ==============================================================================
#define QS_OFF  0
#define SC_OFF  272                      // 4*68
#define KS_OFF  (272 + 4 * 4104)         // 16688
#define RED_OFF (KS_OFF + 128 * 68)      // 25392
#define ATT_SMEM_FLOATS (RED_OFF + 16)   // 25408
#define ATT_SMEM_BYTES  (ATT_SMEM_FLOATS * 4)  // 101632

__global__ void __launch_bounds__(256) attn_kernel(
    const float* __restrict__ ck, const float* __restrict__ cv)
{
    extern __shared__ float sm[];
    float* qs  = sm + QS_OFF;    // [4][68]
    float* sc  = sm + SC_OFF;    // [4][4104]
    float* Ks  = sm + KS_OFF;    // [128][68]
    float* red = sm + RED_OFF;   // [16]

    const int b = blockIdx.x >> 5;
    const int h = blockIdx.x & 31;
    const int tid = threadIdx.x;

    // load q tile (4 rows x 64)
    {
        const int s = tid >> 6, d = tid & 63;
        qs[s * 68 + d] = g_xq[(size_t)(b * SEQ + s) * DMODEL + h * HDIM + d];
    }
    __syncthreads();

    const float* kb = ck + ((size_t)b * CACHE * NHEAD + h) * HDIM;  // + k*2048

    // ---------------- phase 1: scores ----------------
    for (int c0 = 0; c0 < 4224; c0 += 128) {
        // stage 128 key rows (2048 float4 / 256 threads = 8 each)
#pragma unroll
        for (int i = 0; i < 8; i++) {
            const int fid = i * 256 + tid;
            const int r = fid >> 4, c4 = fid & 15;
            const int kk = c0 + r;
            float4 v;
            if (kk < CACHE)
                v = *(const float4*)(kb + (size_t)kk * (NHEAD * HDIM) + c4 * 4);
            else if (kk < NKEY)
                v = *(const float4*)(g_xk + (size_t)(b * SEQ + (kk - CACHE)) * DMODEL
                                     + h * HDIM + c4 * 4);
            else
                v = make_float4(0.f, 0.f, 0.f, 0.f);
            *(float4*)(Ks + r * 68 + c4 * 4) = v;
        }
        __syncthreads();

        // dots: thread = (k_local 0..127, q-half 0..1)
        {
            const int kl = tid & 127;
            const int qh = tid >> 7;
            const int kk = c0 + kl;
            if (kk < NKEY) {
                float a0 = 0.f, a1 = 0.f;
#pragma unroll
                for (int d4 = 0; d4 < 16; d4++) {
                    const float4 kv = *(const float4*)(Ks + kl * 68 + d4 * 4);
                    const float4 q0 = *(const float4*)(qs + (2 * qh) * 68 + d4 * 4);
                    const float4 q1 = *(const float4*)(qs + (2 * qh + 1) * 68 + d4 * 4);
                    a0 += kv.x * q0.x + kv.y * q0.y + kv.z * q0.z + kv.w * q0.w;
                    a1 += kv.x * q1.x + kv.y * q1.y + kv.z * q1.z + kv.w * q1.w;
                }
                float s0 = a0 * 0.125f;   // 1/sqrt(64)
                float s1 = a1 * 0.125f;
                if (kk >= CACHE) {        // causal mask among the 4 new tokens
                    const int j = kk - CACHE;
                    if (j > 2 * qh)     s0 = -1e30f;
                    if (j > 2 * qh + 1) s1 = -1e30f;
                }
                sc[(2 * qh) * 4104 + kk]     = s0;
                sc[(2 * qh + 1) * 4104 + kk] = s1;
            }
        }
        __syncthreads();
    }

    // ---------------- phase 2: softmax (4 rows x 64 threads) ----------------
    const int r = tid >> 6;
    const int lane64 = tid & 63;
    float* row = sc + r * 4104;

    float mx = -1e30f;
    for (int k = lane64; k < NKEY; k += 64) mx = fmaxf(mx, row[k]);
#pragma unroll
    for (int o = 16; o; o >>= 1) mx = fmaxf(mx, __shfl_xor_sync(0xffffffffu, mx, o));
    if ((tid & 31) == 0) red[tid >> 5] = mx;
    __syncthreads();
    mx = fmaxf(red[r * 2], red[r * 2 + 1]);

    float sum = 0.f;
    for (int k = lane64; k < NKEY; k += 64) {
        const float e = __expf(row[k] - mx);
        row[k] = e;
        sum += e;
    }
#pragma unroll
    for (int o = 16; o; o >>= 1) sum += __shfl_xor_sync(0xffffffffu, sum, o);
    if ((tid & 31) == 0) red[8 + (tid >> 5)] = sum;
    __syncthreads();
    const float inv = 1.0f / (red[8 + r * 2] + red[8 + r * 2 + 1]);

    // ---------------- phase 3: AV ----------------
    const int q = r, d = lane64;
    const float* vb = cv + ((size_t)b * CACHE * NHEAD + h) * HDIM + d;
    const float* prow = sc + q * 4104;

    float acc = 0.f;
    for (int k0 = 0; k0 < CACHE; k0 += 16) {
        float vv[16];
#pragma unroll
        for (int j = 0; j < 16; j++)
            vv[j] = vb[(size_t)(k0 + j) * (NHEAD * HDIM)];
#pragma unroll
        for (int j = 0; j < 16; j++)
            acc += prow[k0 + j] * vv[j];
    }
#pragma unroll
    for (int j = 0; j < SEQ; j++)
        acc += prow[CACHE + j] * g_xv[(size_t)(b * SEQ + j) * DMODEL + h * HDIM + d];

    g_attn[(size_t)(b * SEQ + q) * DMODEL + h * HDIM + d] = acc * inv;
}

// ==============================================================================
extern "C" void kernel_launch(void* const* d_in, const int* in_sizes, int n_in,
                              void* d_out, int out_size)
{
    const float* x  = (const float*)d_in[0];
    const float* fc = (const float*)d_in[1];
    const float* fs = (const float*)d_in[2];
    // d_in[3] = mask (re-derived analytically), d_in[10] = start_pos (fixed 4096)
    const float* ck = (const float*)d_in[4];
    const float* cv = (const float*)d_in[5];
    const float* wq = (const float*)d_in[6];
    const float* wk = (const float*)d_in[7];
    const float* wv = (const float*)d_in[8];
    const float* wo = (const float*)d_in[9];
    float* out = (float*)d_out;

    cudaFuncSetAttribute(attn_kernel,
                         cudaFuncAttributeMaxDynamicSharedMemorySize, ATT_SMEM_BYTES);

    qkv_gemm_kernel<<<96, 256>>>(x, wq, wk, wv, fc, fs);
    attn_kernel<<<BATCH * NHEAD, 256, ATT_SMEM_BYTES>>>(ck, cv);
    wo_gemm_kernel<<<128, 256>>>(wo);
    combine_kernel<<<MROWS * DMODEL / 256, 256>>>(out);
}

// round 2
// speedup vs baseline: 2.0135x; 2.0135x over previous
#include <cuda_runtime.h>
#include <cstdint>

// Problem constants
#define BATCH 8
#define SEQ   4
#define DMODEL 2048
#define NHEAD 32
#define HDIM  64
#define CACHE 4096
#define NKEY  (CACHE + SEQ)   // 4100
#define MROWS (BATCH * SEQ)   // 32

// ---------------- scratch (device globals; no allocation allowed) -------------
static __device__ float g_xq[MROWS * DMODEL];
static __device__ float g_xk[MROWS * DMODEL];
static __device__ float g_xv[MROWS * DMODEL];
static __device__ float g_attn[MROWS * DMODEL];
static __device__ float g_part[4][MROWS * DMODEL];

// ---------------- f32x2 helpers (Blackwell packed fp32 FMA) -------------------
__device__ __forceinline__ void ffma2(unsigned long long& d,
                                      unsigned long long a,
                                      unsigned long long b)
{
    asm volatile("fma.rn.f32x2 %0, %1, %2, %0;" : "+l"(d) : "l"(a), "l"(b));
}
__device__ __forceinline__ float2 unpack2(unsigned long long u)
{
    float2 r;
    asm volatile("mov.b64 {%0, %1}, %2;" : "=f"(r.x), "=f"(r.y) : "l"(u));
    return r;
}
union F4 { float4 v; unsigned long long u[2]; };

// ==============================================================================
// GEMM tile core (unchanged from round 1): C[32, 64-tile] = X @ W^T.
// ==============================================================================
__device__ __forceinline__ void gemm_tile(
    const float* __restrict__ X, const float* __restrict__ W,
    float* __restrict__ out, int tile, int c_begin, int c_end,
    bool rope, const float* __restrict__ fc, const float* __restrict__ fs)
{
    __shared__ float Xs[32 * 68];
    __shared__ float Ws[64 * 68];

    const int tid = threadIdx.x;
    const int tx = tid & 31;
    const int ty = tid >> 5;

    unsigned long long acc[4][2];
#pragma unroll
    for (int i = 0; i < 4; i++) { acc[i][0] = 0ull; acc[i][1] = 0ull; }

    float4 px[2], pw[4];
    {
        const int k0 = c_begin * 64;
#pragma unroll
        for (int i = 0; i < 2; i++) {
            int fid = i * 256 + tid; int m = fid >> 4, c4 = fid & 15;
            px[i] = *(const float4*)(X + (size_t)m * DMODEL + k0 + c4 * 4);
        }
#pragma unroll
        for (int i = 0; i < 4; i++) {
            int fid = i * 256 + tid; int n = fid >> 4, c4 = fid & 15;
            pw[i] = *(const float4*)(W + (size_t)(tile * 64 + n) * DMODEL + k0 + c4 * 4);
        }
    }

    for (int c = c_begin; c < c_end; ++c) {
#pragma unroll
        for (int i = 0; i < 2; i++) {
            int fid = i * 256 + tid; int m = fid >> 4, c4 = fid & 15;
            *(float4*)(Xs + m * 68 + c4 * 4) = px[i];
        }
#pragma unroll
        for (int i = 0; i < 4; i++) {
            int fid = i * 256 + tid; int n = fid >> 4, c4 = fid & 15;
            *(float4*)(Ws + n * 68 + c4 * 4) = pw[i];
        }
        __syncthreads();

        if (c + 1 < c_end) {
            const int k0 = (c + 1) * 64;
#pragma unroll
            for (int i = 0; i < 2; i++) {
                int fid = i * 256 + tid; int m = fid >> 4, c4 = fid & 15;
                px[i] = *(const float4*)(X + (size_t)m * DMODEL + k0 + c4 * 4);
            }
#pragma unroll
            for (int i = 0; i < 4; i++) {
                int fid = i * 256 + tid; int n = fid >> 4, c4 = fid & 15;
                pw[i] = *(const float4*)(W + (size_t)(tile * 64 + n) * DMODEL + k0 + c4 * 4);
            }
        }

#pragma unroll
        for (int kk = 0; kk < 64; kk += 8) {
            F4 w00, w01, w10, w11;
            w00.v = *(const float4*)(Ws + tx * 68 + kk);
            w01.v = *(const float4*)(Ws + tx * 68 + kk + 4);
            w10.v = *(const float4*)(Ws + (tx + 32) * 68 + kk);
            w11.v = *(const float4*)(Ws + (tx + 32) * 68 + kk + 4);
#pragma unroll
            for (int i = 0; i < 4; i++) {
                F4 xa, xb;
                xa.v = *(const float4*)(Xs + (ty * 4 + i) * 68 + kk);
                xb.v = *(const float4*)(Xs + (ty * 4 + i) * 68 + kk + 4);
                ffma2(acc[i][0], xa.u[0], w00.u[0]);
                ffma2(acc[i][0], xa.u[1], w00.u[1]);
                ffma2(acc[i][0], xb.u[0], w01.u[0]);
                ffma2(acc[i][0], xb.u[1], w01.u[1]);
                ffma2(acc[i][1], xa.u[0], w10.u[0]);
                ffma2(acc[i][1], xa.u[1], w10.u[1]);
                ffma2(acc[i][1], xb.u[0], w11.u[0]);
                ffma2(acc[i][1], xb.u[1], w11.u[1]);
            }
        }
        __syncthreads();
    }

#pragma unroll
    for (int i = 0; i < 4; i++) {
#pragma unroll
        for (int j = 0; j < 2; j++) {
            float2 h2 = unpack2(acc[i][j]);
            float val = h2.x + h2.y;
            const int nl = tx + j * 32;
            if (rope) {
                float partner = __shfl_xor_sync(0xffffffffu, val, 1);
                const int pidx = nl >> 1;
                const float cth = fc[i * (HDIM / 2) + pidx];
                const float sth = fs[i * (HDIM / 2) + pidx];
                val = ((tx & 1) == 0) ? (val * cth - partner * sth)
                                      : (val * cth + partner * sth);
            }
            out[(size_t)(ty * 4 + i) * DMODEL + tile * 64 + nl] = val;
        }
    }
}

__global__ void __launch_bounds__(256) qkv_gemm_kernel(
    const float* __restrict__ x,
    const float* __restrict__ wq, const float* __restrict__ wk,
    const float* __restrict__ wv,
    const float* __restrict__ fc, const float* __restrict__ fs)
{
    const int g = blockIdx.x >> 5;
    const int tile = blockIdx.x & 31;
    const float* W = (g == 0) ? wq : (g == 1 ? wk : wv);
    float* out = (g == 0) ? g_xq : (g == 1 ? g_xk : g_xv);
    gemm_tile(x, W, out, tile, 0, 32, (g < 2), fc, fs);
}

__global__ void __launch_bounds__(256) wo_gemm_kernel(const float* __restrict__ wo)
{
    const int ks = blockIdx.x >> 5;
    const int tile = blockIdx.x & 31;
    gemm_tile(g_attn, wo, g_part[ks], tile, ks * 8, ks * 8 + 8, false, nullptr, nullptr);
}

__global__ void __launch_bounds__(256) combine_kernel(float* __restrict__ out)
{
    const int i = blockIdx.x * 256 + threadIdx.x;
    out[i] = g_part[0][i] + g_part[1][i] + g_part[2][i] + g_part[3][i];
}

// ==============================================================================
// Attention v2: one block per (b, h). Scores k-major: sc[k][4] (q contiguous).
//   Phase 1: stage 128 keys/chunk (register-prefetch pipelined), f32x2 dots.
//   Phase 2: vectorized softmax over float4 rows (all 4 q at once).
//   Phase 3: AV — warp owns contiguous 512-row V strip, LDG.128 (2 rows/iter),
//            V read exactly once, all 4 q accumulated per lane.
// ==============================================================================
#define SC_ROWS 4104
#define QS_OFF  0
#define SC_OFF  272                       // 4*68 floats for q tile
#define KS_OFF  (SC_OFF + SC_ROWS * 4)    // 16688
#define AVRED_OFF KS_OFF                  // aliases Ks (dead after phase 1)
#define RED_OFF (KS_OFF + 2048)           // 32 warp partials + mx4 + inv4
#define ATT_SMEM_FLOATS (KS_OFF + 128 * 68)   // 25392
#define ATT_SMEM_BYTES  (ATT_SMEM_FLOATS * 4) // 101568

__device__ __forceinline__ float4 ld_key(const float* __restrict__ kb, int b,
                                         int h, int kk, int c4)
{
    if (kk < CACHE)
        return *(const float4*)(kb + (size_t)kk * (NHEAD * HDIM) + c4 * 4);
    if (kk < NKEY)
        return *(const float4*)(g_xk + (size_t)(b * SEQ + (kk - CACHE)) * DMODEL
                                + h * HDIM + c4 * 4);
    return make_float4(0.f, 0.f, 0.f, 0.f);
}

__global__ void __launch_bounds__(256) attn_kernel(
    const float* __restrict__ ck, const float* __restrict__ cv)
{
    extern __shared__ float sm[];
    float* qs    = sm + QS_OFF;     // [4][68]
    float* sc    = sm + SC_OFF;     // [4104][4]
    float* Ks    = sm + KS_OFF;     // [128][68]
    float* avred = sm + AVRED_OFF;  // [8][4][64]  (aliases Ks)
    float* red   = sm + RED_OFF;    // [40]

    const int b = blockIdx.x >> 5;
    const int h = blockIdx.x & 31;
    const int tid = threadIdx.x;

    // load q tile (4 rows x 64)
    {
        const int s = tid >> 6, d = tid & 63;
        qs[s * 68 + d] = g_xq[(size_t)(b * SEQ + s) * DMODEL + h * HDIM + d];
    }
    __syncthreads();

    const float* kb = ck + ((size_t)b * CACHE * NHEAD + h) * HDIM;

    // ---------------- phase 1: scores (k-major) ----------------
    float4 pk[8];
#pragma unroll
    for (int i = 0; i < 8; i++) {
        const int fid = i * 256 + tid;
        pk[i] = ld_key(kb, b, h, fid >> 4, fid & 15);
    }

    const int kl = tid & 127;
    const int qh = tid >> 7;      // 0 -> q{0,1}, 1 -> q{2,3}
    const float* q0r = qs + (2 * qh) * 68;
    const float* q1r = qs + (2 * qh + 1) * 68;

    for (int c0 = 0; c0 < 4224; c0 += 128) {
        // stage prefetched chunk
#pragma unroll
        for (int i = 0; i < 8; i++) {
            const int fid = i * 256 + tid;
            *(float4*)(Ks + (fid >> 4) * 68 + (fid & 15) * 4) = pk[i];
        }
        __syncthreads();

        // prefetch next chunk (hides LDG under the dot compute)
        if (c0 + 128 < 4224) {
#pragma unroll
            for (int i = 0; i < 8; i++) {
                const int fid = i * 256 + tid;
                pk[i] = ld_key(kb, b, h, c0 + 128 + (fid >> 4), fid & 15);
            }
        }

        const int kk = c0 + kl;
        if (kk < NKEY) {
            unsigned long long a0 = 0ull, a1 = 0ull;
#pragma unroll
            for (int d4 = 0; d4 < 16; d4++) {
                F4 kv, v0, v1;
                kv.v = *(const float4*)(Ks + kl * 68 + d4 * 4);
                v0.v = *(const float4*)(q0r + d4 * 4);
                v1.v = *(const float4*)(q1r + d4 * 4);
                ffma2(a0, kv.u[0], v0.u[0]);
                ffma2(a0, kv.u[1], v0.u[1]);
                ffma2(a1, kv.u[0], v1.u[0]);
                ffma2(a1, kv.u[1], v1.u[1]);
            }
            float2 h0 = unpack2(a0), h1 = unpack2(a1);
            float s0 = (h0.x + h0.y) * 0.125f;  // 1/sqrt(64)
            float s1 = (h1.x + h1.y) * 0.125f;
            if (kk >= CACHE) {                  // causal mask on new tokens
                const int j = kk - CACHE;
                if (j > 2 * qh)     s0 = -1e30f;
                if (j > 2 * qh + 1) s1 = -1e30f;
            }
            *(float2*)(sc + kk * 4 + 2 * qh) = make_float2(s0, s1);
        } else if (kk < SC_ROWS) {
            *(float2*)(sc + kk * 4 + 2 * qh) = make_float2(-1e30f, -1e30f);
        }
        __syncthreads();
    }

    // ---------------- phase 2: softmax (vectorized, all 4 q at once) --------
    float4* sc4 = (float4*)sc;
    const int wid = tid >> 5, lane = tid & 31;

    float4 m4 = make_float4(-1e30f, -1e30f, -1e30f, -1e30f);
#pragma unroll
    for (int i = 0; i < 17; i++) {
        const int k = tid + i * 256;
        if (k < SC_ROWS) {
            const float4 v = sc4[k];
            m4.x = fmaxf(m4.x, v.x); m4.y = fmaxf(m4.y, v.y);
            m4.z = fmaxf(m4.z, v.z); m4.w = fmaxf(m4.w, v.w);
        }
    }
#pragma unroll
    for (int o = 16; o; o >>= 1) {
        m4.x = fmaxf(m4.x, __shfl_xor_sync(0xffffffffu, m4.x, o));
        m4.y = fmaxf(m4.y, __shfl_xor_sync(0xffffffffu, m4.y, o));
        m4.z = fmaxf(m4.z, __shfl_xor_sync(0xffffffffu, m4.z, o));
        m4.w = fmaxf(m4.w, __shfl_xor_sync(0xffffffffu, m4.w, o));
    }
    if (lane == 0) *(float4*)(red + wid * 4) = m4;
    __syncthreads();
    if (tid == 0) {
        float4 t = *(float4*)red;
#pragma unroll
        for (int w = 1; w < 8; w++) {
            const float4 v = *(float4*)(red + w * 4);
            t.x = fmaxf(t.x, v.x); t.y = fmaxf(t.y, v.y);
            t.z = fmaxf(t.z, v.z); t.w = fmaxf(t.w, v.w);
        }
        *(float4*)(red + 32) = t;
    }
    __syncthreads();
    const float4 mx4 = *(float4*)(red + 32);

    float4 s4 = make_float4(0.f, 0.f, 0.f, 0.f);
#pragma unroll
    for (int i = 0; i < 17; i++) {
        const int k = tid + i * 256;
        if (k < SC_ROWS) {
            float4 v = sc4[k];
            v.x = __expf(v.x - mx4.x); v.y = __expf(v.y - mx4.y);
            v.z = __expf(v.z - mx4.z); v.w = __expf(v.w - mx4.w);
            sc4[k] = v;
            s4.x += v.x; s4.y += v.y; s4.z += v.z; s4.w += v.w;
        }
    }
#pragma unroll
    for (int o = 16; o; o >>= 1) {
        s4.x += __shfl_xor_sync(0xffffffffu, s4.x, o);
        s4.y += __shfl_xor_sync(0xffffffffu, s4.y, o);
        s4.z += __shfl_xor_sync(0xffffffffu, s4.z, o);
        s4.w += __shfl_xor_sync(0xffffffffu, s4.w, o);
    }
    if (lane == 0) *(float4*)(red + wid * 4) = s4;
    __syncthreads();
    if (tid == 0) {
        float4 t = *(float4*)red;
#pragma unroll
        for (int w = 1; w < 8; w++) {
            const float4 v = *(float4*)(red + w * 4);
            t.x += v.x; t.y += v.y; t.z += v.z; t.w += v.w;
        }
        t.x = 1.0f / t.x; t.y = 1.0f / t.y; t.z = 1.0f / t.z; t.w = 1.0f / t.w;
        *(float4*)(red + 36) = t;
    }
    __syncthreads();

    // ---------------- phase 3: AV (V read exactly once, LDG.128) ------------
    {
        const int lane16 = lane & 15;
        const int half = lane >> 4;
        const float4* vb4 = (const float4*)(cv + ((size_t)b * CACHE * NHEAD + h) * HDIM);

        float4 a0 = make_float4(0,0,0,0), a1 = a0, a2 = a0, a3 = a0;
        const int kbase = wid * 512;
        for (int k0 = kbase; k0 < kbase + 512; k0 += 16) {
            float4 v[8];
#pragma unroll
            for (int i = 0; i < 8; i++) {
                const int row = k0 + 2 * i + half;
                v[i] = vb4[(size_t)row * (NHEAD * HDIM / 4) + lane16];
            }
#pragma unroll
            for (int i = 0; i < 8; i++) {
                const int row = k0 + 2 * i + half;
                const float4 p = *(const float4*)(sc + row * 4);
                a0.x += p.x * v[i].x; a0.y += p.x * v[i].y; a0.z += p.x * v[i].z; a0.w += p.x * v[i].w;
                a1.x += p.y * v[i].x; a1.y += p.y * v[i].y; a1.z += p.y * v[i].z; a1.w += p.y * v[i].w;
                a2.x += p.z * v[i].x; a2.y += p.z * v[i].y; a2.z += p.z * v[i].z; a2.w += p.z * v[i].w;
                a3.x += p.w * v[i].x; a3.y += p.w * v[i].y; a3.z += p.w * v[i].z; a3.w += p.w * v[i].w;
            }
        }
        // fold the two row-parities (half=1 lanes into half=0 lanes)
#pragma unroll
        for (int c = 0; c < 1; c++) { /* unrolled manually below */ }
        a0.x += __shfl_down_sync(0xffffffffu, a0.x, 16);
        a0.y += __shfl_down_sync(0xffffffffu, a0.y, 16);
        a0.z += __shfl_down_sync(0xffffffffu, a0.z, 16);
        a0.w += __shfl_down_sync(0xffffffffu, a0.w, 16);
        a1.x += __shfl_down_sync(0xffffffffu, a1.x, 16);
        a1.y += __shfl_down_sync(0xffffffffu, a1.y, 16);
        a1.z += __shfl_down_sync(0xffffffffu, a1.z, 16);
        a1.w += __shfl_down_sync(0xffffffffu, a1.w, 16);
        a2.x += __shfl_down_sync(0xffffffffu, a2.x, 16);
        a2.y += __shfl_down_sync(0xffffffffu, a2.y, 16);
        a2.z += __shfl_down_sync(0xffffffffu, a2.z, 16);
        a2.w += __shfl_down_sync(0xffffffffu, a2.w, 16);
        a3.x += __shfl_down_sync(0xffffffffu, a3.x, 16);
        a3.y += __shfl_down_sync(0xffffffffu, a3.y, 16);
        a3.z += __shfl_down_sync(0xffffffffu, a3.z, 16);
        a3.w += __shfl_down_sync(0xffffffffu, a3.w, 16);
        if (half == 0) {
            *(float4*)(avred + wid * 256 + 0 * 64 + lane16 * 4) = a0;
            *(float4*)(avred + wid * 256 + 1 * 64 + lane16 * 4) = a1;
            *(float4*)(avred + wid * 256 + 2 * 64 + lane16 * 4) = a2;
            *(float4*)(avred + wid * 256 + 3 * 64 + lane16 * 4) = a3;
        }
    }
    __syncthreads();

    // final combine: cross-warp sum + new-token V + normalize
    {
        const int q = tid >> 6, d = tid & 63;
        float r = 0.f;
#pragma unroll
        for (int w = 0; w < 8; w++) r += avred[w * 256 + q * 64 + d];
#pragma unroll
        for (int j = 0; j < SEQ; j++)
            r += sc[(CACHE + j) * 4 + q]
               * g_xv[(size_t)(b * SEQ + j) * DMODEL + h * HDIM + d];
        const float inv = red[36 + q];
        g_attn[(size_t)(b * SEQ + q) * DMODEL + h * HDIM + d] = r * inv;
    }
}

// ==============================================================================
extern "C" void kernel_launch(void* const* d_in, const int* in_sizes, int n_in,
                              void* d_out, int out_size)
{
    const float* x  = (const float*)d_in[0];
    const float* fc = (const float*)d_in[1];
    const float* fs = (const float*)d_in[2];
    const float* ck = (const float*)d_in[4];
    const float* cv = (const float*)d_in[5];
    const float* wq = (const float*)d_in[6];
    const float* wk = (const float*)d_in[7];
    const float* wv = (const float*)d_in[8];
    const float* wo = (const float*)d_in[9];
    float* out = (float*)d_out;

    cudaFuncSetAttribute(attn_kernel,
                         cudaFuncAttributeMaxDynamicSharedMemorySize, ATT_SMEM_BYTES);

    qkv_gemm_kernel<<<96, 256>>>(x, wq, wk, wv, fc, fs);
    attn_kernel<<<BATCH * NHEAD, 256, ATT_SMEM_BYTES>>>(ck, cv);
    wo_gemm_kernel<<<128, 256>>>(wo);
    combine_kernel<<<MROWS * DMODEL / 256, 256>>>(out);
}

// round 3
// speedup vs baseline: 2.3350x; 1.1597x over previous
#include <cuda_runtime.h>
#include <cstdint>

// Problem constants
#define BATCH 8
#define SEQ   4
#define DMODEL 2048
#define NHEAD 32
#define HDIM  64
#define CACHE 4096
#define NKEY  (CACHE + SEQ)   // 4100
#define MROWS (BATCH * SEQ)   // 32
#define SPLIT 8
#define KPB   512             // cache keys per attention block

// ---------------- scratch (device globals; no allocation allowed) -------------
static __device__ float g_xq[MROWS * DMODEL];
static __device__ float g_xk[MROWS * DMODEL];
static __device__ float g_xv[MROWS * DMODEL];
static __device__ float g_attn[MROWS * DMODEL];
static __device__ float g_part[4][MROWS * DMODEL];
static __device__ float g_po[BATCH * NHEAD * SPLIT * SEQ * HDIM];  // unnormalized O
static __device__ float g_ms[BATCH * NHEAD * SPLIT * SEQ * 2];     // (m, s)

// ---------------- f32x2 helpers (Blackwell packed fp32 FMA) -------------------
__device__ __forceinline__ void ffma2(unsigned long long& d,
                                      unsigned long long a,
                                      unsigned long long b)
{
    asm volatile("fma.rn.f32x2 %0, %1, %2, %0;" : "+l"(d) : "l"(a), "l"(b));
}
__device__ __forceinline__ float2 unpack2(unsigned long long u)
{
    float2 r;
    asm volatile("mov.b64 {%0, %1}, %2;" : "=f"(r.x), "=f"(r.y) : "l"(u));
    return r;
}
__device__ __forceinline__ unsigned long long pack2(float a, float b)
{
    unsigned long long u;
    asm volatile("mov.b64 %0, {%1, %2};" : "=l"(u) : "f"(a), "f"(b));
    return u;
}
union F4 { float4 v; unsigned long long u[2]; };

// ==============================================================================
// GEMM tile core (unchanged): C[32, 64-tile] = X @ W^T over K chunk range.
// ==============================================================================
__device__ __forceinline__ void gemm_tile(
    const float* __restrict__ X, const float* __restrict__ W,
    float* __restrict__ out, int tile, int c_begin, int c_end,
    bool rope, const float* __restrict__ fc, const float* __restrict__ fs)
{
    __shared__ float Xs[32 * 68];
    __shared__ float Ws[64 * 68];

    const int tid = threadIdx.x;
    const int tx = tid & 31;
    const int ty = tid >> 5;

    unsigned long long acc[4][2];
#pragma unroll
    for (int i = 0; i < 4; i++) { acc[i][0] = 0ull; acc[i][1] = 0ull; }

    float4 px[2], pw[4];
    {
        const int k0 = c_begin * 64;
#pragma unroll
        for (int i = 0; i < 2; i++) {
            int fid = i * 256 + tid; int m = fid >> 4, c4 = fid & 15;
            px[i] = *(const float4*)(X + (size_t)m * DMODEL + k0 + c4 * 4);
        }
#pragma unroll
        for (int i = 0; i < 4; i++) {
            int fid = i * 256 + tid; int n = fid >> 4, c4 = fid & 15;
            pw[i] = *(const float4*)(W + (size_t)(tile * 64 + n) * DMODEL + k0 + c4 * 4);
        }
    }

    for (int c = c_begin; c < c_end; ++c) {
#pragma unroll
        for (int i = 0; i < 2; i++) {
            int fid = i * 256 + tid; int m = fid >> 4, c4 = fid & 15;
            *(float4*)(Xs + m * 68 + c4 * 4) = px[i];
        }
#pragma unroll
        for (int i = 0; i < 4; i++) {
            int fid = i * 256 + tid; int n = fid >> 4, c4 = fid & 15;
            *(float4*)(Ws + n * 68 + c4 * 4) = pw[i];
        }
        __syncthreads();

        if (c + 1 < c_end) {
            const int k0 = (c + 1) * 64;
#pragma unroll
            for (int i = 0; i < 2; i++) {
                int fid = i * 256 + tid; int m = fid >> 4, c4 = fid & 15;
                px[i] = *(const float4*)(X + (size_t)m * DMODEL + k0 + c4 * 4);
            }
#pragma unroll
            for (int i = 0; i < 4; i++) {
                int fid = i * 256 + tid; int n = fid >> 4, c4 = fid & 15;
                pw[i] = *(const float4*)(W + (size_t)(tile * 64 + n) * DMODEL + k0 + c4 * 4);
            }
        }

#pragma unroll
        for (int kk = 0; kk < 64; kk += 8) {
            F4 w00, w01, w10, w11;
            w00.v = *(const float4*)(Ws + tx * 68 + kk);
            w01.v = *(const float4*)(Ws + tx * 68 + kk + 4);
            w10.v = *(const float4*)(Ws + (tx + 32) * 68 + kk);
            w11.v = *(const float4*)(Ws + (tx + 32) * 68 + kk + 4);
#pragma unroll
            for (int i = 0; i < 4; i++) {
                F4 xa, xb;
                xa.v = *(const float4*)(Xs + (ty * 4 + i) * 68 + kk);
                xb.v = *(const float4*)(Xs + (ty * 4 + i) * 68 + kk + 4);
                ffma2(acc[i][0], xa.u[0], w00.u[0]);
                ffma2(acc[i][0], xa.u[1], w00.u[1]);
                ffma2(acc[i][0], xb.u[0], w01.u[0]);
                ffma2(acc[i][0], xb.u[1], w01.u[1]);
                ffma2(acc[i][1], xa.u[0], w10.u[0]);
                ffma2(acc[i][1], xa.u[1], w10.u[1]);
                ffma2(acc[i][1], xb.u[0], w11.u[0]);
                ffma2(acc[i][1], xb.u[1], w11.u[1]);
            }
        }
        __syncthreads();
    }

#pragma unroll
    for (int i = 0; i < 4; i++) {
#pragma unroll
        for (int j = 0; j < 2; j++) {
            float2 h2 = unpack2(acc[i][j]);
            float val = h2.x + h2.y;
            const int nl = tx + j * 32;
            if (rope) {
                float partner = __shfl_xor_sync(0xffffffffu, val, 1);
                const int pidx = nl >> 1;
                const float cth = fc[i * (HDIM / 2) + pidx];
                const float sth = fs[i * (HDIM / 2) + pidx];
                val = ((tx & 1) == 0) ? (val * cth - partner * sth)
                                      : (val * cth + partner * sth);
            }
            out[(size_t)(ty * 4 + i) * DMODEL + tile * 64 + nl] = val;
        }
    }
}

__global__ void __launch_bounds__(256) qkv_gemm_kernel(
    const float* __restrict__ x,
    const float* __restrict__ wq, const float* __restrict__ wk,
    const float* __restrict__ wv,
    const float* __restrict__ fc, const float* __restrict__ fs)
{
    const int g = blockIdx.x >> 5;
    const int tile = blockIdx.x & 31;
    const float* W = (g == 0) ? wq : (g == 1 ? wk : wv);
    float* out = (g == 0) ? g_xq : (g == 1 ? g_xk : g_xv);
    gemm_tile(x, W, out, tile, 0, 32, (g < 2), fc, fs);
}

__global__ void __launch_bounds__(256) wo_gemm_kernel(const float* __restrict__ wo)
{
    const int ks = blockIdx.x >> 5;
    const int tile = blockIdx.x & 31;
    gemm_tile(g_attn, wo, g_part[ks], tile, ks * 8, ks * 8 + 8, false, nullptr, nullptr);
}

__global__ void __launch_bounds__(256) combine_kernel(float* __restrict__ out)
{
    const int i = blockIdx.x * 256 + threadIdx.x;
    out[i] = g_part[0][i] + g_part[1][i] + g_part[2][i] + g_part[3][i];
}

// ==============================================================================
// Attention v3 (split-K flash): block = (b, h, split of 512 cache keys).
//   Phase 1: 4 pipelined chunks of 128 keys -> scores sc[516][4] (k-major).
//   Phase 2: local softmax over 516 rows -> m4, s4.
//   Phase 3: AV over own 512 rows (warp = 64-row strip, f32x2), unnormalized.
//   Output: g_po (o partial), g_ms (m, s). Merge in attn_combine_kernel.
// ==============================================================================
#define SC_ROWS 520
#define QS_OFF  0
#define SC_OFF  272                          // q tile 4*68
#define KS_OFF  (SC_OFF + SC_ROWS * 4)       // 2352
#define AVRED_OFF KS_OFF                     // aliases Ks (dead after phase 1)
#define RED_OFF (KS_OFF + 128 * 68)          // 11056
#define ATT_SMEM_FLOATS (RED_OFF + 40)       // 11096
#define ATT_SMEM_BYTES  (ATT_SMEM_FLOATS * 4) // 44384

__global__ void __launch_bounds__(256) attn_kernel(
    const float* __restrict__ ck, const float* __restrict__ cv)
{
    extern __shared__ float sm[];
    float* qs    = sm + QS_OFF;     // [4][68]
    float* sc    = sm + SC_OFF;     // [520][4]
    float* Ks    = sm + KS_OFF;     // [128][68]
    float* avred = sm + AVRED_OFF;  // [8][4][64] (aliases Ks)
    float* red   = sm + RED_OFF;    // [40]

    const int bh    = blockIdx.x >> 3;
    const int split = blockIdx.x & 7;
    const int b = bh >> 5;
    const int h = bh & 31;
    const int tid = threadIdx.x;
    const int kbase = split * KPB;

    // q tile
    {
        const int s = tid >> 6, d = tid & 63;
        qs[s * 68 + d] = g_xq[(size_t)(b * SEQ + s) * DMODEL + h * HDIM + d];
    }
    __syncthreads();

    const float* kb = ck + ((size_t)b * CACHE * NHEAD + h) * HDIM;

    // ---------------- phase 1: scores (cache keys only, no bounds checks) ---
    float4 pk[8];
#pragma unroll
    for (int i = 0; i < 8; i++) {
        const int fid = i * 256 + tid;
        pk[i] = *(const float4*)(kb + (size_t)(kbase + (fid >> 4)) * (NHEAD * HDIM)
                                 + (fid & 15) * 4);
    }

    const int kl = tid & 127;
    const int qh = tid >> 7;
    const float* q0r = qs + (2 * qh) * 68;
    const float* q1r = qs + (2 * qh + 1) * 68;

#pragma unroll
    for (int c0 = 0; c0 < KPB; c0 += 128) {
#pragma unroll
        for (int i = 0; i < 8; i++) {
            const int fid = i * 256 + tid;
            *(float4*)(Ks + (fid >> 4) * 68 + (fid & 15) * 4) = pk[i];
        }
        __syncthreads();

        if (c0 + 128 < KPB) {
#pragma unroll
            for (int i = 0; i < 8; i++) {
                const int fid = i * 256 + tid;
                pk[i] = *(const float4*)(kb + (size_t)(kbase + c0 + 128 + (fid >> 4))
                                         * (NHEAD * HDIM) + (fid & 15) * 4);
            }
        }

        unsigned long long a0 = 0ull, a1 = 0ull;
#pragma unroll
        for (int d4 = 0; d4 < 16; d4++) {
            F4 kv, v0, v1;
            kv.v = *(const float4*)(Ks + kl * 68 + d4 * 4);
            v0.v = *(const float4*)(q0r + d4 * 4);
            v1.v = *(const float4*)(q1r + d4 * 4);
            ffma2(a0, kv.u[0], v0.u[0]);
            ffma2(a0, kv.u[1], v0.u[1]);
            ffma2(a1, kv.u[0], v1.u[0]);
            ffma2(a1, kv.u[1], v1.u[1]);
        }
        float2 h0 = unpack2(a0), h1 = unpack2(a1);
        *(float2*)(sc + (c0 + kl) * 4 + 2 * qh) =
            make_float2((h0.x + h0.y) * 0.125f, (h1.x + h1.y) * 0.125f);
        __syncthreads();
    }

    // new-token scores (split 7) / padding rows 512..515
    if (split == SPLIT - 1) {
        if (tid < 16) {
            const int q = tid >> 2, j = tid & 3;
            const float* kx = g_xk + (size_t)(b * SEQ + j) * DMODEL + h * HDIM;
            float acc = 0.f;
#pragma unroll
            for (int d = 0; d < HDIM; d++) acc += qs[q * 68 + d] * kx[d];
            float s = acc * 0.125f;
            if (j > q) s = -1e30f;
            sc[(KPB + j) * 4 + q] = s;
        }
    } else if (tid < 16) {
        sc[KPB * 4 + tid] = -1e30f;
    }
    __syncthreads();

    const int NR = KPB + 4;   // 516 score rows

    // ---------------- phase 2: local softmax (all 4 q at once) --------------
    float4* sc4 = (float4*)sc;
    const int wid = tid >> 5, lane = tid & 31;

    float4 m4 = make_float4(-1e30f, -1e30f, -1e30f, -1e30f);
#pragma unroll
    for (int i = 0; i < 3; i++) {
        const int k = tid + i * 256;
        if (k < NR) {
            const float4 v = sc4[k];
            m4.x = fmaxf(m4.x, v.x); m4.y = fmaxf(m4.y, v.y);
            m4.z = fmaxf(m4.z, v.z); m4.w = fmaxf(m4.w, v.w);
        }
    }
#pragma unroll
    for (int o = 16; o; o >>= 1) {
        m4.x = fmaxf(m4.x, __shfl_xor_sync(0xffffffffu, m4.x, o));
        m4.y = fmaxf(m4.y, __shfl_xor_sync(0xffffffffu, m4.y, o));
        m4.z = fmaxf(m4.z, __shfl_xor_sync(0xffffffffu, m4.z, o));
        m4.w = fmaxf(m4.w, __shfl_xor_sync(0xffffffffu, m4.w, o));
    }
    if (lane == 0) *(float4*)(red + wid * 4) = m4;
    __syncthreads();
    if (tid == 0) {
        float4 t = *(float4*)red;
#pragma unroll
        for (int w = 1; w < 8; w++) {
            const float4 v = *(float4*)(red + w * 4);
            t.x = fmaxf(t.x, v.x); t.y = fmaxf(t.y, v.y);
            t.z = fmaxf(t.z, v.z); t.w = fmaxf(t.w, v.w);
        }
        *(float4*)(red + 32) = t;
    }
    __syncthreads();
    const float4 mx4 = *(float4*)(red + 32);

    float4 s4 = make_float4(0.f, 0.f, 0.f, 0.f);
#pragma unroll
    for (int i = 0; i < 3; i++) {
        const int k = tid + i * 256;
        if (k < NR) {
            float4 v = sc4[k];
            v.x = __expf(v.x - mx4.x); v.y = __expf(v.y - mx4.y);
            v.z = __expf(v.z - mx4.z); v.w = __expf(v.w - mx4.w);
            sc4[k] = v;
            s4.x += v.x; s4.y += v.y; s4.z += v.z; s4.w += v.w;
        }
    }
#pragma unroll
    for (int o = 16; o; o >>= 1) {
        s4.x += __shfl_xor_sync(0xffffffffu, s4.x, o);
        s4.y += __shfl_xor_sync(0xffffffffu, s4.y, o);
        s4.z += __shfl_xor_sync(0xffffffffu, s4.z, o);
        s4.w += __shfl_xor_sync(0xffffffffu, s4.w, o);
    }
    if (lane == 0) *(float4*)(red + wid * 4) = s4;
    __syncthreads();
    if (tid == 0) {
        float4 t = *(float4*)red;
#pragma unroll
        for (int w = 1; w < 8; w++) {
            const float4 v = *(float4*)(red + w * 4);
            t.x += v.x; t.y += v.y; t.z += v.z; t.w += v.w;
        }
        *(float4*)(red + 36) = t;   // raw sums (not inverted)
    }
    __syncthreads();

    // ---------------- phase 3: AV over own 512 rows (f32x2) -----------------
    {
        const int lane16 = lane & 15;
        const int half = lane >> 4;
        const float4* vb4 = (const float4*)(cv + ((size_t)b * CACHE * NHEAD + h) * HDIM);

        unsigned long long acc[4][2];
#pragma unroll
        for (int q = 0; q < 4; q++) { acc[q][0] = 0ull; acc[q][1] = 0ull; }

        const int strip = wid * 64;
        for (int k0 = strip; k0 < strip + 64; k0 += 16) {
            float4 v[8];
#pragma unroll
            for (int i = 0; i < 8; i++) {
                const int row = k0 + 2 * i + half;
                v[i] = vb4[(size_t)(kbase + row) * (NHEAD * HDIM / 4) + lane16];
            }
#pragma unroll
            for (int i = 0; i < 8; i++) {
                const int row = k0 + 2 * i + half;
                const float4 p = *(const float4*)(sc + row * 4);
                F4 vv; vv.v = v[i];
                const unsigned long long p0 = pack2(p.x, p.x);
                const unsigned long long p1 = pack2(p.y, p.y);
                const unsigned long long p2 = pack2(p.z, p.z);
                const unsigned long long p3 = pack2(p.w, p.w);
                ffma2(acc[0][0], vv.u[0], p0); ffma2(acc[0][1], vv.u[1], p0);
                ffma2(acc[1][0], vv.u[0], p1); ffma2(acc[1][1], vv.u[1], p1);
                ffma2(acc[2][0], vv.u[0], p2); ffma2(acc[2][1], vv.u[1], p2);
                ffma2(acc[3][0], vv.u[0], p3); ffma2(acc[3][1], vv.u[1], p3);
            }
        }
        __syncthreads();   // Ks region dead -> safe to alias as avred

#pragma unroll
        for (int q = 0; q < 4; q++) {
            float2 lo = unpack2(acc[q][0]);
            float2 hi = unpack2(acc[q][1]);
            lo.x += __shfl_down_sync(0xffffffffu, lo.x, 16);
            lo.y += __shfl_down_sync(0xffffffffu, lo.y, 16);
            hi.x += __shfl_down_sync(0xffffffffu, hi.x, 16);
            hi.y += __shfl_down_sync(0xffffffffu, hi.y, 16);
            if (half == 0)
                *(float4*)(avred + wid * 256 + q * 64 + lane16 * 4) =
                    make_float4(lo.x, lo.y, hi.x, hi.y);
        }
    }
    __syncthreads();

    // ---------------- output: unnormalized partial + (m, s) -----------------
    {
        const int q = tid >> 6, d = tid & 63;
        float r = 0.f;
#pragma unroll
        for (int w = 0; w < 8; w++) r += avred[w * 256 + q * 64 + d];
        if (split == SPLIT - 1) {
#pragma unroll
            for (int j = 0; j < SEQ; j++)
                r += sc[(KPB + j) * 4 + q]
                   * g_xv[(size_t)(b * SEQ + j) * DMODEL + h * HDIM + d];
        }
        const int base = (bh * SPLIT + split) * SEQ + q;
        g_po[(size_t)base * HDIM + d] = r;
        if (d == 0) {
            g_ms[base * 2 + 0] = red[32 + q];
            g_ms[base * 2 + 1] = red[36 + q];
        }
    }
}

// merge the 8 split partials per (b, h): block = bh, thread = (q, d)
__global__ void __launch_bounds__(256) attn_combine_kernel()
{
    const int bh = blockIdx.x;
    const int tid = threadIdx.x;
    const int q = tid >> 6, d = tid & 63;

    float mi[SPLIT], si[SPLIT];
    float M = -1e30f;
#pragma unroll
    for (int i = 0; i < SPLIT; i++) {
        const int base = (bh * SPLIT + i) * SEQ + q;
        mi[i] = g_ms[base * 2 + 0];
        si[i] = g_ms[base * 2 + 1];
        M = fmaxf(M, mi[i]);
    }
    float num = 0.f, den = 0.f;
#pragma unroll
    for (int i = 0; i < SPLIT; i++) {
        const float w = __expf(mi[i] - M);
        const int base = (bh * SPLIT + i) * SEQ + q;
        num += g_po[(size_t)base * HDIM + d] * w;
        den += si[i] * w;
    }
    const int b = bh >> 5, h = bh & 31;
    g_attn[(size_t)(b * SEQ + q) * DMODEL + h * HDIM + d] = num / den;
}

// ==============================================================================
extern "C" void kernel_launch(void* const* d_in, const int* in_sizes, int n_in,
                              void* d_out, int out_size)
{
    const float* x  = (const float*)d_in[0];
    const float* fc = (const float*)d_in[1];
    const float* fs = (const float*)d_in[2];
    const float* ck = (const float*)d_in[4];
    const float* cv = (const float*)d_in[5];
    const float* wq = (const float*)d_in[6];
    const float* wk = (const float*)d_in[7];
    const float* wv = (const float*)d_in[8];
    const float* wo = (const float*)d_in[9];
    float* out = (float*)d_out;

    qkv_gemm_kernel<<<96, 256>>>(x, wq, wk, wv, fc, fs);
    attn_kernel<<<BATCH * NHEAD * SPLIT, 256, ATT_SMEM_BYTES>>>(ck, cv);
    attn_combine_kernel<<<BATCH * NHEAD, 256>>>();
    wo_gemm_kernel<<<128, 256>>>(wo);
    combine_kernel<<<MROWS * DMODEL / 256, 256>>>(out);
}

// round 4
// speedup vs baseline: 2.6847x; 1.1497x over previous
#include <cuda_runtime.h>
#include <cstdint>

// Problem constants
#define BATCH 8
#define SEQ   4
#define DMODEL 2048
#define NHEAD 32
#define HDIM  64
#define CACHE 4096
#define NKEY  (CACHE + SEQ)   // 4100
#define MROWS (BATCH * SEQ)   // 32
#define SPLIT 8
#define KPB   512             // cache keys per attention block
#define QKV_SPLIT 4
#define WO_SPLIT  8

// ---------------- scratch (device globals; no allocation allowed) -------------
static __device__ float g_xq[MROWS * DMODEL];
static __device__ float g_xk[MROWS * DMODEL];
static __device__ float g_xv[MROWS * DMODEL];
static __device__ float g_attn[MROWS * DMODEL];
static __device__ float g_qkvp[3][QKV_SPLIT][MROWS * DMODEL];   // qkv split-K partials
static __device__ float g_part[WO_SPLIT][MROWS * DMODEL];        // wo split-K partials
static __device__ float g_po[BATCH * NHEAD * SPLIT * SEQ * HDIM];
static __device__ float g_ms[BATCH * NHEAD * SPLIT * SEQ * 2];

// ---------------- f32x2 helpers (Blackwell packed fp32 FMA) -------------------
__device__ __forceinline__ void ffma2(unsigned long long& d,
                                      unsigned long long a,
                                      unsigned long long b)
{
    asm volatile("fma.rn.f32x2 %0, %1, %2, %0;" : "+l"(d) : "l"(a), "l"(b));
}
__device__ __forceinline__ float2 unpack2(unsigned long long u)
{
    float2 r;
    asm volatile("mov.b64 {%0, %1}, %2;" : "=f"(r.x), "=f"(r.y) : "l"(u));
    return r;
}
__device__ __forceinline__ unsigned long long pack2(float a, float b)
{
    unsigned long long u;
    asm volatile("mov.b64 %0, {%1, %2};" : "=l"(u) : "f"(a), "f"(b));
    return u;
}
union F4 { float4 v; unsigned long long u[2]; };

// ==============================================================================
// GEMM tile core: C[32, 64-tile] = X @ W^T over K chunk range (no epilogue op).
// ==============================================================================
__device__ __forceinline__ void gemm_tile(
    const float* __restrict__ X, const float* __restrict__ W,
    float* __restrict__ out, int tile, int c_begin, int c_end)
{
    __shared__ float Xs[32 * 68];
    __shared__ float Ws[64 * 68];

    const int tid = threadIdx.x;
    const int tx = tid & 31;
    const int ty = tid >> 5;

    unsigned long long acc[4][2];
#pragma unroll
    for (int i = 0; i < 4; i++) { acc[i][0] = 0ull; acc[i][1] = 0ull; }

    float4 px[2], pw[4];
    {
        const int k0 = c_begin * 64;
#pragma unroll
        for (int i = 0; i < 2; i++) {
            int fid = i * 256 + tid; int m = fid >> 4, c4 = fid & 15;
            px[i] = *(const float4*)(X + (size_t)m * DMODEL + k0 + c4 * 4);
        }
#pragma unroll
        for (int i = 0; i < 4; i++) {
            int fid = i * 256 + tid; int n = fid >> 4, c4 = fid & 15;
            pw[i] = *(const float4*)(W + (size_t)(tile * 64 + n) * DMODEL + k0 + c4 * 4);
        }
    }

    for (int c = c_begin; c < c_end; ++c) {
#pragma unroll
        for (int i = 0; i < 2; i++) {
            int fid = i * 256 + tid; int m = fid >> 4, c4 = fid & 15;
            *(float4*)(Xs + m * 68 + c4 * 4) = px[i];
        }
#pragma unroll
        for (int i = 0; i < 4; i++) {
            int fid = i * 256 + tid; int n = fid >> 4, c4 = fid & 15;
            *(float4*)(Ws + n * 68 + c4 * 4) = pw[i];
        }
        __syncthreads();

        if (c + 1 < c_end) {
            const int k0 = (c + 1) * 64;
#pragma unroll
            for (int i = 0; i < 2; i++) {
                int fid = i * 256 + tid; int m = fid >> 4, c4 = fid & 15;
                px[i] = *(const float4*)(X + (size_t)m * DMODEL + k0 + c4 * 4);
            }
#pragma unroll
            for (int i = 0; i < 4; i++) {
                int fid = i * 256 + tid; int n = fid >> 4, c4 = fid & 15;
                pw[i] = *(const float4*)(W + (size_t)(tile * 64 + n) * DMODEL + k0 + c4 * 4);
            }
        }

#pragma unroll
        for (int kk = 0; kk < 64; kk += 8) {
            F4 w00, w01, w10, w11;
            w00.v = *(const float4*)(Ws + tx * 68 + kk);
            w01.v = *(const float4*)(Ws + tx * 68 + kk + 4);
            w10.v = *(const float4*)(Ws + (tx + 32) * 68 + kk);
            w11.v = *(const float4*)(Ws + (tx + 32) * 68 + kk + 4);
#pragma unroll
            for (int i = 0; i < 4; i++) {
                F4 xa, xb;
                xa.v = *(const float4*)(Xs + (ty * 4 + i) * 68 + kk);
                xb.v = *(const float4*)(Xs + (ty * 4 + i) * 68 + kk + 4);
                ffma2(acc[i][0], xa.u[0], w00.u[0]);
                ffma2(acc[i][0], xa.u[1], w00.u[1]);
                ffma2(acc[i][0], xb.u[0], w01.u[0]);
                ffma2(acc[i][0], xb.u[1], w01.u[1]);
                ffma2(acc[i][1], xa.u[0], w10.u[0]);
                ffma2(acc[i][1], xa.u[1], w10.u[1]);
                ffma2(acc[i][1], xb.u[0], w11.u[0]);
                ffma2(acc[i][1], xb.u[1], w11.u[1]);
            }
        }
        __syncthreads();
    }

#pragma unroll
    for (int i = 0; i < 4; i++) {
#pragma unroll
        for (int j = 0; j < 2; j++) {
            float2 h2 = unpack2(acc[i][j]);
            out[(size_t)(ty * 4 + i) * DMODEL + tile * 64 + tx + j * 32] = h2.x + h2.y;
        }
    }
}

// qkv: grid 384 = 3 mats x 4 splits x 32 tiles
__global__ void __launch_bounds__(256) qkv_gemm_kernel(
    const float* __restrict__ x,
    const float* __restrict__ wq, const float* __restrict__ wk,
    const float* __restrict__ wv)
{
    const int tile = blockIdx.x & 31;
    const int ks   = (blockIdx.x >> 5) & 3;
    const int g    = blockIdx.x >> 7;
    const float* W = (g == 0) ? wq : (g == 1 ? wk : wv);
    gemm_tile(x, W, g_qkvp[g][ks], tile, ks * 8, ks * 8 + 8);
}

// qkv combine + RoPE: grid 384 x 256 threads, thread = one even/odd column pair
__global__ void __launch_bounds__(256) qkv_combine_kernel(
    const float* __restrict__ fc, const float* __restrict__ fs)
{
    const int idx = blockIdx.x * 256 + threadIdx.x;      // 0..98303
    const int g    = idx >> 15;                          // /32768 pairs per matrix
    const int rrem = idx & 32767;
    const int row  = rrem >> 10;
    const int pcol = rrem & 1023;
    const size_t off = (size_t)row * DMODEL + pcol * 2;

    float2 e = *(const float2*)(&g_qkvp[g][0][off]);
#pragma unroll
    for (int ks = 1; ks < QKV_SPLIT; ks++) {
        const float2 t = *(const float2*)(&g_qkvp[g][ks][off]);
        e.x += t.x; e.y += t.y;
    }

    float* dst = (g == 0) ? g_xq : (g == 1 ? g_xk : g_xv);
    if (g < 2) {
        const int s = row & 3;
        const int p = pcol & 31;
        const float c  = fc[s * 32 + p];
        const float sn = fs[s * 32 + p];
        const float o0 = e.x * c - e.y * sn;
        const float o1 = e.x * sn + e.y * c;
        e = make_float2(o0, o1);
    }
    *(float2*)(dst + off) = e;
}

// wo: grid 256 = 8 splits x 32 tiles
__global__ void __launch_bounds__(256) wo_gemm_kernel(const float* __restrict__ wo)
{
    const int ks = blockIdx.x >> 5;
    const int tile = blockIdx.x & 31;
    gemm_tile(g_attn, wo, g_part[ks], tile, ks * 4, ks * 4 + 4);
}

__global__ void __launch_bounds__(256) combine_kernel(float* __restrict__ out)
{
    const int i = blockIdx.x * 256 + threadIdx.x;
    float r = 0.f;
#pragma unroll
    for (int ks = 0; ks < WO_SPLIT; ks++) r += g_part[ks][i];
    out[i] = r;
}

// ==============================================================================
// Attention v4 (split-K flash, register-resident QK):
//   block = (b, h, split of 512 cache keys), 256 threads.
//   Phase 1: 8-lane group owns a key; lanes LDG their 32B of the row, dot
//            against register-held q (pre-scaled), 3-level shfl reduce.
//            No smem staging, no in-loop syncs.
//   Phase 2: local softmax over 516 rows (4 q at once).
//   Phase 3: AV over own 512 rows (warp = 64-row strip, f32x2), unnormalized.
// ==============================================================================
__global__ void __launch_bounds__(256) attn_kernel(
    const float* __restrict__ ck, const float* __restrict__ cv)
{
    __shared__ float qs[4 * 68];
    __shared__ float sc[520 * 4];
    __shared__ float avred[8 * 256];
    __shared__ float red[40];

    const int bh    = blockIdx.x >> 3;
    const int split = blockIdx.x & 7;
    const int b = bh >> 5;
    const int h = bh & 31;
    const int tid = threadIdx.x;
    const int kbase = split * KPB;
    const int wid = tid >> 5, lane = tid & 31;

    // q tile, pre-scaled by 1/sqrt(HDIM)
    {
        const int s = tid >> 6, d = tid & 63;
        qs[s * 68 + d] = g_xq[(size_t)(b * SEQ + s) * DMODEL + h * HDIM + d] * 0.125f;
    }
    __syncthreads();

    const float* kb = ck + ((size_t)b * CACHE * NHEAD + h) * HDIM;

    // ---------------- phase 1: register-resident QK dots --------------------
    {
        const int g = lane >> 3;      // key within 4-key round
        const int s = lane & 7;       // 32B segment within key row

        F4 qr[4][2];
#pragma unroll
        for (int qi = 0; qi < 4; qi++) {
            qr[qi][0].v = *(const float4*)(qs + qi * 68 + s * 4);
            qr[qi][1].v = *(const float4*)(qs + qi * 68 + s * 4 + 32);
        }

        const float* kptr = kb + (size_t)(kbase + wid * 64 + g) * (NHEAD * HDIM) + s * 4;

#pragma unroll 4
        for (int r = 0; r < 16; r++) {
            F4 k0, k1;
            k0.v = *(const float4*)(kptr + (size_t)r * 4 * (NHEAD * HDIM));
            k1.v = *(const float4*)(kptr + (size_t)r * 4 * (NHEAD * HDIM) + 32);
            float p[4];
#pragma unroll
            for (int qi = 0; qi < 4; qi++) {
                unsigned long long a = 0ull;
                ffma2(a, k0.u[0], qr[qi][0].u[0]);
                ffma2(a, k0.u[1], qr[qi][0].u[1]);
                ffma2(a, k1.u[0], qr[qi][1].u[0]);
                ffma2(a, k1.u[1], qr[qi][1].u[1]);
                const float2 t = unpack2(a);
                p[qi] = t.x + t.y;
            }
#pragma unroll
            for (int o = 1; o <= 4; o <<= 1) {
#pragma unroll
                for (int qi = 0; qi < 4; qi++)
                    p[qi] += __shfl_xor_sync(0xffffffffu, p[qi], o);
            }
            if (s == 0)
                *(float4*)(sc + (wid * 64 + r * 4 + g) * 4) =
                    make_float4(p[0], p[1], p[2], p[3]);
        }
    }

    // new-token scores (split 7) / padding rows 512..515
    if (split == SPLIT - 1) {
        if (tid < 16) {
            const int q = tid >> 2, j = tid & 3;
            const float* kx = g_xk + (size_t)(b * SEQ + j) * DMODEL + h * HDIM;
            float acc = 0.f;
#pragma unroll
            for (int d = 0; d < HDIM; d++) acc += qs[q * 68 + d] * kx[d];
            float sv = acc;                // q pre-scaled
            if (j > q) sv = -1e30f;
            sc[(KPB + j) * 4 + q] = sv;
        }
    } else if (tid < 16) {
        sc[KPB * 4 + tid] = -1e30f;
    }
    __syncthreads();

    const int NR = KPB + 4;   // 516 score rows

    // ---------------- phase 2: local softmax (all 4 q at once) --------------
    float4* sc4 = (float4*)sc;

    float4 m4 = make_float4(-1e30f, -1e30f, -1e30f, -1e30f);
#pragma unroll
    for (int i = 0; i < 3; i++) {
        const int k = tid + i * 256;
        if (k < NR) {
            const float4 v = sc4[k];
            m4.x = fmaxf(m4.x, v.x); m4.y = fmaxf(m4.y, v.y);
            m4.z = fmaxf(m4.z, v.z); m4.w = fmaxf(m4.w, v.w);
        }
    }
#pragma unroll
    for (int o = 16; o; o >>= 1) {
        m4.x = fmaxf(m4.x, __shfl_xor_sync(0xffffffffu, m4.x, o));
        m4.y = fmaxf(m4.y, __shfl_xor_sync(0xffffffffu, m4.y, o));
        m4.z = fmaxf(m4.z, __shfl_xor_sync(0xffffffffu, m4.z, o));
        m4.w = fmaxf(m4.w, __shfl_xor_sync(0xffffffffu, m4.w, o));
    }
    if (lane == 0) *(float4*)(red + wid * 4) = m4;
    __syncthreads();
    if (tid == 0) {
        float4 t = *(float4*)red;
#pragma unroll
        for (int w = 1; w < 8; w++) {
            const float4 v = *(float4*)(red + w * 4);
            t.x = fmaxf(t.x, v.x); t.y = fmaxf(t.y, v.y);
            t.z = fmaxf(t.z, v.z); t.w = fmaxf(t.w, v.w);
        }
        *(float4*)(red + 32) = t;
    }
    __syncthreads();
    const float4 mx4 = *(float4*)(red + 32);

    float4 s4 = make_float4(0.f, 0.f, 0.f, 0.f);
#pragma unroll
    for (int i = 0; i < 3; i++) {
        const int k = tid + i * 256;
        if (k < NR) {
            float4 v = sc4[k];
            v.x = __expf(v.x - mx4.x); v.y = __expf(v.y - mx4.y);
            v.z = __expf(v.z - mx4.z); v.w = __expf(v.w - mx4.w);
            sc4[k] = v;
            s4.x += v.x; s4.y += v.y; s4.z += v.z; s4.w += v.w;
        }
    }
#pragma unroll
    for (int o = 16; o; o >>= 1) {
        s4.x += __shfl_xor_sync(0xffffffffu, s4.x, o);
        s4.y += __shfl_xor_sync(0xffffffffu, s4.y, o);
        s4.z += __shfl_xor_sync(0xffffffffu, s4.z, o);
        s4.w += __shfl_xor_sync(0xffffffffu, s4.w, o);
    }
    if (lane == 0) *(float4*)(red + wid * 4) = s4;
    __syncthreads();
    if (tid == 0) {
        float4 t = *(float4*)red;
#pragma unroll
        for (int w = 1; w < 8; w++) {
            const float4 v = *(float4*)(red + w * 4);
            t.x += v.x; t.y += v.y; t.z += v.z; t.w += v.w;
        }
        *(float4*)(red + 36) = t;   // raw sums
    }
    __syncthreads();

    // ---------------- phase 3: AV over own 512 rows (f32x2) -----------------
    {
        const int lane16 = lane & 15;
        const int half = lane >> 4;
        const float4* vb4 = (const float4*)(cv + ((size_t)b * CACHE * NHEAD + h) * HDIM);

        unsigned long long acc[4][2];
#pragma unroll
        for (int q = 0; q < 4; q++) { acc[q][0] = 0ull; acc[q][1] = 0ull; }

        const int strip = wid * 64;
        for (int k0 = strip; k0 < strip + 64; k0 += 16) {
            float4 v[8];
#pragma unroll
            for (int i = 0; i < 8; i++) {
                const int row = k0 + 2 * i + half;
                v[i] = vb4[(size_t)(kbase + row) * (NHEAD * HDIM / 4) + lane16];
            }
#pragma unroll
            for (int i = 0; i < 8; i++) {
                const int row = k0 + 2 * i + half;
                const float4 p = *(const float4*)(sc + row * 4);
                F4 vv; vv.v = v[i];
                const unsigned long long p0 = pack2(p.x, p.x);
                const unsigned long long p1 = pack2(p.y, p.y);
                const unsigned long long p2 = pack2(p.z, p.z);
                const unsigned long long p3 = pack2(p.w, p.w);
                ffma2(acc[0][0], vv.u[0], p0); ffma2(acc[0][1], vv.u[1], p0);
                ffma2(acc[1][0], vv.u[0], p1); ffma2(acc[1][1], vv.u[1], p1);
                ffma2(acc[2][0], vv.u[0], p2); ffma2(acc[2][1], vv.u[1], p2);
                ffma2(acc[3][0], vv.u[0], p3); ffma2(acc[3][1], vv.u[1], p3);
            }
        }

#pragma unroll
        for (int q = 0; q < 4; q++) {
            float2 lo = unpack2(acc[q][0]);
            float2 hi = unpack2(acc[q][1]);
            lo.x += __shfl_down_sync(0xffffffffu, lo.x, 16);
            lo.y += __shfl_down_sync(0xffffffffu, lo.y, 16);
            hi.x += __shfl_down_sync(0xffffffffu, hi.x, 16);
            hi.y += __shfl_down_sync(0xffffffffu, hi.y, 16);
            if (half == 0)
                *(float4*)(avred + wid * 256 + q * 64 + lane16 * 4) =
                    make_float4(lo.x, lo.y, hi.x, hi.y);
        }
    }
    __syncthreads();

    // ---------------- output: unnormalized partial + (m, s) -----------------
    {
        const int q = tid >> 6, d = tid & 63;
        float r = 0.f;
#pragma unroll
        for (int w = 0; w < 8; w++) r += avred[w * 256 + q * 64 + d];
        if (split == SPLIT - 1) {
#pragma unroll
            for (int j = 0; j < SEQ; j++)
                r += sc[(KPB + j) * 4 + q]
                   * g_xv[(size_t)(b * SEQ + j) * DMODEL + h * HDIM + d];
        }
        const int base = (bh * SPLIT + split) * SEQ + q;
        g_po[(size_t)base * HDIM + d] = r;
        if (d == 0) {
            g_ms[base * 2 + 0] = red[32 + q];
            g_ms[base * 2 + 1] = red[36 + q];
        }
    }
}

// merge the 8 split partials per (b, h): block = bh, thread = (q, d)
__global__ void __launch_bounds__(256) attn_combine_kernel()
{
    const int bh = blockIdx.x;
    const int tid = threadIdx.x;
    const int q = tid >> 6, d = tid & 63;

    float mi[SPLIT], si[SPLIT];
    float M = -1e30f;
#pragma unroll
    for (int i = 0; i < SPLIT; i++) {
        const int base = (bh * SPLIT + i) * SEQ + q;
        mi[i] = g_ms[base * 2 + 0];
        si[i] = g_ms[base * 2 + 1];
        M = fmaxf(M, mi[i]);
    }
    float num = 0.f, den = 0.f;
#pragma unroll
    for (int i = 0; i < SPLIT; i++) {
        const float w = __expf(mi[i] - M);
        const int base = (bh * SPLIT + i) * SEQ + q;
        num += g_po[(size_t)base * HDIM + d] * w;
        den += si[i] * w;
    }
    const int b = bh >> 5, h = bh & 31;
    g_attn[(size_t)(b * SEQ + q) * DMODEL + h * HDIM + d] = num / den;
}

// ==============================================================================
extern "C" void kernel_launch(void* const* d_in, const int* in_sizes, int n_in,
                              void* d_out, int out_size)
{
    const float* x  = (const float*)d_in[0];
    const float* fc = (const float*)d_in[1];
    const float* fs = (const float*)d_in[2];
    const float* ck = (const float*)d_in[4];
    const float* cv = (const float*)d_in[5];
    const float* wq = (const float*)d_in[6];
    const float* wk = (const float*)d_in[7];
    const float* wv = (const float*)d_in[8];
    const float* wo = (const float*)d_in[9];
    float* out = (float*)d_out;

    qkv_gemm_kernel<<<3 * QKV_SPLIT * 32, 256>>>(x, wq, wk, wv);
    qkv_combine_kernel<<<384, 256>>>(fc, fs);
    attn_kernel<<<BATCH * NHEAD * SPLIT, 256>>>(ck, cv);
    attn_combine_kernel<<<BATCH * NHEAD, 256>>>();
    wo_gemm_kernel<<<WO_SPLIT * 32, 256>>>(wo);
    combine_kernel<<<MROWS * DMODEL / 256, 256>>>(out);
}

// round 5
// speedup vs baseline: 2.7129x; 1.0105x over previous
#include <cuda_runtime.h>
#include <cstdint>

// Problem constants
#define BATCH 8
#define SEQ   4
#define DMODEL 2048
#define NHEAD 32
#define HDIM  64
#define CACHE 4096
#define MROWS (BATCH * SEQ)   // 32
#define SPLIT 8
#define KPB   512             // cache keys per attention block
#define QKV_SPLIT 4
#define WO_SPLIT  8

// ---------------- scratch (device globals; no allocation allowed) -------------
static __device__ float g_attn[MROWS * DMODEL];
static __device__ float g_qkvp[3][QKV_SPLIT][MROWS * DMODEL];   // qkv split-K partials
static __device__ float g_part[WO_SPLIT][MROWS * DMODEL];        // wo split-K partials
static __device__ float g_po[BATCH * NHEAD * SPLIT * SEQ * HDIM];
static __device__ float g_s [BATCH * NHEAD * SPLIT * SEQ];       // exp-sum per split

// ---------------- f32x2 helpers (Blackwell packed fp32 FMA) -------------------
__device__ __forceinline__ void ffma2(unsigned long long& d,
                                      unsigned long long a,
                                      unsigned long long b)
{
    asm volatile("fma.rn.f32x2 %0, %1, %2, %0;" : "+l"(d) : "l"(a), "l"(b));
}
__device__ __forceinline__ float2 unpack2(unsigned long long u)
{
    float2 r;
    asm volatile("mov.b64 {%0, %1}, %2;" : "=f"(r.x), "=f"(r.y) : "l"(u));
    return r;
}
__device__ __forceinline__ unsigned long long pack2(float a, float b)
{
    unsigned long long u;
    asm volatile("mov.b64 %0, {%1, %2};" : "=l"(u) : "f"(a), "f"(b));
    return u;
}
union F4 { float4 v; unsigned long long u[2]; };

// ==============================================================================
// GEMM tile core: C[32, 64-tile] = X @ W^T over K chunk range.
// ==============================================================================
__device__ __forceinline__ void gemm_tile(
    const float* __restrict__ X, const float* __restrict__ W,
    float* __restrict__ out, int tile, int c_begin, int c_end)
{
    __shared__ float Xs[32 * 68];
    __shared__ float Ws[64 * 68];

    const int tid = threadIdx.x;
    const int tx = tid & 31;
    const int ty = tid >> 5;

    unsigned long long acc[4][2];
#pragma unroll
    for (int i = 0; i < 4; i++) { acc[i][0] = 0ull; acc[i][1] = 0ull; }

    float4 px[2], pw[4];
    {
        const int k0 = c_begin * 64;
#pragma unroll
        for (int i = 0; i < 2; i++) {
            int fid = i * 256 + tid; int m = fid >> 4, c4 = fid & 15;
            px[i] = *(const float4*)(X + (size_t)m * DMODEL + k0 + c4 * 4);
        }
#pragma unroll
        for (int i = 0; i < 4; i++) {
            int fid = i * 256 + tid; int n = fid >> 4, c4 = fid & 15;
            pw[i] = *(const float4*)(W + (size_t)(tile * 64 + n) * DMODEL + k0 + c4 * 4);
        }
    }

    for (int c = c_begin; c < c_end; ++c) {
#pragma unroll
        for (int i = 0; i < 2; i++) {
            int fid = i * 256 + tid; int m = fid >> 4, c4 = fid & 15;
            *(float4*)(Xs + m * 68 + c4 * 4) = px[i];
        }
#pragma unroll
        for (int i = 0; i < 4; i++) {
            int fid = i * 256 + tid; int n = fid >> 4, c4 = fid & 15;
            *(float4*)(Ws + n * 68 + c4 * 4) = pw[i];
        }
        __syncthreads();

        if (c + 1 < c_end) {
            const int k0 = (c + 1) * 64;
#pragma unroll
            for (int i = 0; i < 2; i++) {
                int fid = i * 256 + tid; int m = fid >> 4, c4 = fid & 15;
                px[i] = *(const float4*)(X + (size_t)m * DMODEL + k0 + c4 * 4);
            }
#pragma unroll
            for (int i = 0; i < 4; i++) {
                int fid = i * 256 + tid; int n = fid >> 4, c4 = fid & 15;
                pw[i] = *(const float4*)(W + (size_t)(tile * 64 + n) * DMODEL + k0 + c4 * 4);
            }
        }

#pragma unroll
        for (int kk = 0; kk < 64; kk += 8) {
            F4 w00, w01, w10, w11;
            w00.v = *(const float4*)(Ws + tx * 68 + kk);
            w01.v = *(const float4*)(Ws + tx * 68 + kk + 4);
            w10.v = *(const float4*)(Ws + (tx + 32) * 68 + kk);
            w11.v = *(const float4*)(Ws + (tx + 32) * 68 + kk + 4);
#pragma unroll
            for (int i = 0; i < 4; i++) {
                F4 xa, xb;
                xa.v = *(const float4*)(Xs + (ty * 4 + i) * 68 + kk);
                xb.v = *(const float4*)(Xs + (ty * 4 + i) * 68 + kk + 4);
                ffma2(acc[i][0], xa.u[0], w00.u[0]);
                ffma2(acc[i][0], xa.u[1], w00.u[1]);
                ffma2(acc[i][0], xb.u[0], w01.u[0]);
                ffma2(acc[i][0], xb.u[1], w01.u[1]);
                ffma2(acc[i][1], xa.u[0], w10.u[0]);
                ffma2(acc[i][1], xa.u[1], w10.u[1]);
                ffma2(acc[i][1], xb.u[0], w11.u[0]);
                ffma2(acc[i][1], xb.u[1], w11.u[1]);
            }
        }
        __syncthreads();
    }

#pragma unroll
    for (int i = 0; i < 4; i++) {
#pragma unroll
        for (int j = 0; j < 2; j++) {
            float2 h2 = unpack2(acc[i][j]);
            out[(size_t)(ty * 4 + i) * DMODEL + tile * 64 + tx + j * 32] = h2.x + h2.y;
        }
    }
}

// qkv: grid 384 = 3 mats x 4 splits x 32 tiles (writes raw partials)
__global__ void __launch_bounds__(256) qkv_gemm_kernel(
    const float* __restrict__ x,
    const float* __restrict__ wq, const float* __restrict__ wk,
    const float* __restrict__ wv)
{
    const int tile = blockIdx.x & 31;
    const int ks   = (blockIdx.x >> 5) & 3;
    const int g    = blockIdx.x >> 7;
    const float* W = (g == 0) ? wq : (g == 1 ? wk : wv);
    gemm_tile(x, W, g_qkvp[g][ks], tile, ks * 8, ks * 8 + 8);
}

// wo: grid 256 = 8 splits x 32 tiles
__global__ void __launch_bounds__(256) wo_gemm_kernel(const float* __restrict__ wo)
{
    const int ks = blockIdx.x >> 5;
    const int tile = blockIdx.x & 31;
    gemm_tile(g_attn, wo, g_part[ks], tile, ks * 4, ks * 4 + 4);
}

__global__ void __launch_bounds__(256) combine_kernel(float* __restrict__ out)
{
    const int i = blockIdx.x * 256 + threadIdx.x;
    float r = 0.f;
#pragma unroll
    for (int ks = 0; ks < WO_SPLIT; ks++) r += g_part[ks][i];
    out[i] = r;
}

// ==============================================================================
// Attention v5 (split-K flash, no-max softmax, fused exp):
//   block = (b, h, split of 512 cache keys), 256 threads.
//   Prologue: combine q split-partials + RoPE (+ k,v new tokens on split 7).
//   Phase 1: register-resident QK dots -> butterfly reduce -> exp -> sc,
//            running exp-sums in registers. No max pass, no sc sweeps.
//   Phase 3: AV over own 512 rows (f32x2), unnormalized. Output po + s.
// ==============================================================================
__global__ void __launch_bounds__(256) attn_kernel(
    const float* __restrict__ ck, const float* __restrict__ cv,
    const float* __restrict__ fc, const float* __restrict__ fs)
{
    __shared__ float qs[4 * 68];
    __shared__ float kx[4 * 68];
    __shared__ float vx[4 * 68];
    __shared__ float sc[520 * 4];
    __shared__ float avred[8 * 256];
    __shared__ float red[40];

    const int bh    = blockIdx.x >> 3;
    const int split = blockIdx.x & 7;
    const int b = bh >> 5;
    const int h = bh & 31;
    const int tid = threadIdx.x;
    const int kbase = split * KPB;
    const int wid = tid >> 5, lane = tid & 31;

    // ---------------- prologue: combine qkv partials + RoPE -----------------
    if (tid < 128) {
        const int s = tid >> 5, p = tid & 31;
        const size_t off = (size_t)(b * SEQ + s) * DMODEL + h * HDIM + 2 * p;
        float2 e = *(const float2*)(&g_qkvp[0][0][off]);
#pragma unroll
        for (int ks = 1; ks < QKV_SPLIT; ks++) {
            const float2 t = *(const float2*)(&g_qkvp[0][ks][off]);
            e.x += t.x; e.y += t.y;
        }
        const float c  = fc[s * 32 + p];
        const float sn = fs[s * 32 + p];
        qs[s * 68 + 2 * p]     = (e.x * c - e.y * sn) * 0.125f;
        qs[s * 68 + 2 * p + 1] = (e.x * sn + e.y * c) * 0.125f;
    } else if (split == SPLIT - 1) {
        const int t2 = tid - 128;
        const int s = t2 >> 5, p = t2 & 31;
        const size_t off = (size_t)(b * SEQ + s) * DMODEL + h * HDIM + 2 * p;
        // new-token K (+RoPE)
        float2 e = *(const float2*)(&g_qkvp[1][0][off]);
#pragma unroll
        for (int ks = 1; ks < QKV_SPLIT; ks++) {
            const float2 t = *(const float2*)(&g_qkvp[1][ks][off]);
            e.x += t.x; e.y += t.y;
        }
        const float c  = fc[s * 32 + p];
        const float sn = fs[s * 32 + p];
        kx[s * 68 + 2 * p]     = e.x * c - e.y * sn;
        kx[s * 68 + 2 * p + 1] = e.x * sn + e.y * c;
        // new-token V
        float2 v = *(const float2*)(&g_qkvp[2][0][off]);
#pragma unroll
        for (int ks = 1; ks < QKV_SPLIT; ks++) {
            const float2 t = *(const float2*)(&g_qkvp[2][ks][off]);
            v.x += t.x; v.y += t.y;
        }
        vx[s * 68 + 2 * p]     = v.x;
        vx[s * 68 + 2 * p + 1] = v.y;
    }
    __syncthreads();

    const float* kb = ck + ((size_t)b * CACHE * NHEAD + h) * HDIM;

    // ---------------- phase 1: QK dots -> exp -> sc, running sums -----------
    {
        const int g = lane >> 3;      // key within 4-key round
        const int s = lane & 7;       // 32B segment within key row

        F4 qr[4][2];
#pragma unroll
        for (int qi = 0; qi < 4; qi++) {
            qr[qi][0].v = *(const float4*)(qs + qi * 68 + s * 4);
            qr[qi][1].v = *(const float4*)(qs + qi * 68 + s * 4 + 32);
        }

        const float* kptr = kb + (size_t)(kbase + wid * 64 + g) * (NHEAD * HDIM) + s * 4;

        float ssum = 0.f;     // lanes with s<4 accumulate exp-sum for qi=s
#pragma unroll 4
        for (int r = 0; r < 16; r++) {
            F4 k0, k1;
            k0.v = *(const float4*)(kptr + (size_t)r * 4 * (NHEAD * HDIM));
            k1.v = *(const float4*)(kptr + (size_t)r * 4 * (NHEAD * HDIM) + 32);
            float p0, p1, p2, p3;
            {
                unsigned long long a = 0ull;
                ffma2(a, k0.u[0], qr[0][0].u[0]); ffma2(a, k0.u[1], qr[0][0].u[1]);
                ffma2(a, k1.u[0], qr[0][1].u[0]); ffma2(a, k1.u[1], qr[0][1].u[1]);
                const float2 t = unpack2(a); p0 = t.x + t.y;
            }
            {
                unsigned long long a = 0ull;
                ffma2(a, k0.u[0], qr[1][0].u[0]); ffma2(a, k0.u[1], qr[1][0].u[1]);
                ffma2(a, k1.u[0], qr[1][1].u[0]); ffma2(a, k1.u[1], qr[1][1].u[1]);
                const float2 t = unpack2(a); p1 = t.x + t.y;
            }
            {
                unsigned long long a = 0ull;
                ffma2(a, k0.u[0], qr[2][0].u[0]); ffma2(a, k0.u[1], qr[2][0].u[1]);
                ffma2(a, k1.u[0], qr[2][1].u[0]); ffma2(a, k1.u[1], qr[2][1].u[1]);
                const float2 t = unpack2(a); p2 = t.x + t.y;
            }
            {
                unsigned long long a = 0ull;
                ffma2(a, k0.u[0], qr[3][0].u[0]); ffma2(a, k0.u[1], qr[3][0].u[1]);
                ffma2(a, k1.u[0], qr[3][1].u[0]); ffma2(a, k1.u[1], qr[3][1].u[1]);
                const float2 t = unpack2(a); p3 = t.x + t.y;
            }
#pragma unroll
            for (int o = 1; o <= 4; o <<= 1) {
                p0 += __shfl_xor_sync(0xffffffffu, p0, o);
                p1 += __shfl_xor_sync(0xffffffffu, p1, o);
                p2 += __shfl_xor_sync(0xffffffffu, p2, o);
                p3 += __shfl_xor_sync(0xffffffffu, p3, o);
            }
            // lane s (0..3) handles qi=s: one MUFU per round
            const float pa = (s & 1) ? p1 : p0;
            const float pb = (s & 1) ? p3 : p2;
            const float pv = (s & 2) ? pb : pa;
            const float e = __expf(pv);
            if (s < 4) {
                ssum += e;
                sc[(wid * 64 + r * 4 + g) * 4 + s] = e;
            }
        }
        // reduce exp-sums across the 4 groups -> lanes 0..3 hold warp totals
        ssum += __shfl_xor_sync(0xffffffffu, ssum, 8);
        ssum += __shfl_xor_sync(0xffffffffu, ssum, 16);
        if (lane < 4) red[wid * 4 + lane] = ssum;
    }

    // new-token exp-scores (split 7) / zero padding rows 512..515
    if (split == SPLIT - 1) {
        if (tid < 16) {
            const int q = tid >> 2, j = tid & 3;
            float acc = 0.f;
#pragma unroll
            for (int d = 0; d < HDIM; d++) acc += qs[q * 68 + d] * kx[j * 68 + d];
            sc[(KPB + j) * 4 + q] = (j > q) ? 0.f : __expf(acc);
        }
    } else if (tid < 16) {
        sc[KPB * 4 + tid] = 0.f;
    }
    __syncthreads();

    // total exp-sum per q (incl. new tokens)
    if (tid < 4) {
        float t = 0.f;
#pragma unroll
        for (int w = 0; w < 8; w++) t += red[w * 4 + tid];
#pragma unroll
        for (int j = 0; j < SEQ; j++) t += sc[(KPB + j) * 4 + tid];
        red[32 + tid] = t;
    }

    // ---------------- phase 3: AV over own 512 rows (f32x2) -----------------
    {
        const int lane16 = lane & 15;
        const int half = lane >> 4;
        const float4* vb4 = (const float4*)(cv + ((size_t)b * CACHE * NHEAD + h) * HDIM);

        unsigned long long acc[4][2];
#pragma unroll
        for (int q = 0; q < 4; q++) { acc[q][0] = 0ull; acc[q][1] = 0ull; }

        const int strip = wid * 64;
        for (int k0 = strip; k0 < strip + 64; k0 += 16) {
            float4 v[8];
#pragma unroll
            for (int i = 0; i < 8; i++) {
                const int row = k0 + 2 * i + half;
                v[i] = vb4[(size_t)(kbase + row) * (NHEAD * HDIM / 4) + lane16];
            }
#pragma unroll
            for (int i = 0; i < 8; i++) {
                const int row = k0 + 2 * i + half;
                const float4 p = *(const float4*)(sc + row * 4);
                F4 vv; vv.v = v[i];
                const unsigned long long p0 = pack2(p.x, p.x);
                const unsigned long long p1 = pack2(p.y, p.y);
                const unsigned long long p2 = pack2(p.z, p.z);
                const unsigned long long p3 = pack2(p.w, p.w);
                ffma2(acc[0][0], vv.u[0], p0); ffma2(acc[0][1], vv.u[1], p0);
                ffma2(acc[1][0], vv.u[0], p1); ffma2(acc[1][1], vv.u[1], p1);
                ffma2(acc[2][0], vv.u[0], p2); ffma2(acc[2][1], vv.u[1], p2);
                ffma2(acc[3][0], vv.u[0], p3); ffma2(acc[3][1], vv.u[1], p3);
            }
        }

#pragma unroll
        for (int q = 0; q < 4; q++) {
            float2 lo = unpack2(acc[q][0]);
            float2 hi = unpack2(acc[q][1]);
            lo.x += __shfl_down_sync(0xffffffffu, lo.x, 16);
            lo.y += __shfl_down_sync(0xffffffffu, lo.y, 16);
            hi.x += __shfl_down_sync(0xffffffffu, hi.x, 16);
            hi.y += __shfl_down_sync(0xffffffffu, hi.y, 16);
            if (half == 0)
                *(float4*)(avred + wid * 256 + q * 64 + lane16 * 4) =
                    make_float4(lo.x, lo.y, hi.x, hi.y);
        }
    }
    __syncthreads();

    // ---------------- output: unnormalized partial + s ----------------------
    {
        const int q = tid >> 6, d = tid & 63;
        float r = 0.f;
#pragma unroll
        for (int w = 0; w < 8; w++) r += avred[w * 256 + q * 64 + d];
        if (split == SPLIT - 1) {
#pragma unroll
            for (int j = 0; j < SEQ; j++)
                r += sc[(KPB + j) * 4 + q] * vx[j * 68 + d];
        }
        const int base = (bh * SPLIT + split) * SEQ + q;
        g_po[(size_t)base * HDIM + d] = r;
        if (d == 0) g_s[base] = red[32 + q];
    }
}

// merge the 8 split partials per (b, h): pure sum (no max bookkeeping)
__global__ void __launch_bounds__(256) attn_combine_kernel()
{
    const int bh = blockIdx.x;
    const int tid = threadIdx.x;
    const int q = tid >> 6, d = tid & 63;

    float num = 0.f, den = 0.f;
#pragma unroll
    for (int i = 0; i < SPLIT; i++) {
        const int base = (bh * SPLIT + i) * SEQ + q;
        num += g_po[(size_t)base * HDIM + d];
        den += g_s[base];
    }
    const int b = bh >> 5, h = bh & 31;
    g_attn[(size_t)(b * SEQ + q) * DMODEL + h * HDIM + d] = num / den;
}

// ==============================================================================
extern "C" void kernel_launch(void* const* d_in, const int* in_sizes, int n_in,
                              void* d_out, int out_size)
{
    const float* x  = (const float*)d_in[0];
    const float* fc = (const float*)d_in[1];
    const float* fs = (const float*)d_in[2];
    const float* ck = (const float*)d_in[4];
    const float* cv = (const float*)d_in[5];
    const float* wq = (const float*)d_in[6];
    const float* wk = (const float*)d_in[7];
    const float* wv = (const float*)d_in[8];
    const float* wo = (const float*)d_in[9];
    float* out = (float*)d_out;

    qkv_gemm_kernel<<<3 * QKV_SPLIT * 32, 256>>>(x, wq, wk, wv);
    attn_kernel<<<BATCH * NHEAD * SPLIT, 256>>>(ck, cv, fc, fs);
    attn_combine_kernel<<<BATCH * NHEAD, 256>>>();
    wo_gemm_kernel<<<WO_SPLIT * 32, 256>>>(wo);
    combine_kernel<<<MROWS * DMODEL / 256, 256>>>(out);
}

// round 6
// speedup vs baseline: 2.7547x; 1.0154x over previous
#include <cuda_runtime.h>
#include <cstdint>

// Problem constants
#define BATCH 8
#define SEQ   4
#define DMODEL 2048
#define NHEAD 32
#define HDIM  64
#define CACHE 4096
#define MROWS (BATCH * SEQ)   // 32
#define SPLIT 8
#define KPB   512             // cache keys per attention block
#define QKV_SPLIT 4
#define WO_SPLIT  8

// ---------------- scratch (device globals; no allocation allowed) -------------
static __device__ float g_attn[MROWS * DMODEL];
static __device__ float g_qkvp[3][QKV_SPLIT][MROWS * DMODEL];
static __device__ float g_part[WO_SPLIT][MROWS * DMODEL];
static __device__ float g_po[BATCH * NHEAD * SPLIT * SEQ * HDIM];
static __device__ float g_s [BATCH * NHEAD * SPLIT * SEQ];

// ---------------- f32x2 helpers -----------------------------------------------
__device__ __forceinline__ void ffma2(unsigned long long& d,
                                      unsigned long long a,
                                      unsigned long long b)
{
    asm volatile("fma.rn.f32x2 %0, %1, %2, %0;" : "+l"(d) : "l"(a), "l"(b));
}
__device__ __forceinline__ float2 unpack2(unsigned long long u)
{
    float2 r;
    asm volatile("mov.b64 {%0, %1}, %2;" : "=f"(r.x), "=f"(r.y) : "l"(u));
    return r;
}
__device__ __forceinline__ unsigned long long pack2(float a, float b)
{
    unsigned long long u;
    asm volatile("mov.b64 %0, {%1, %2};" : "=l"(u) : "f"(a), "f"(b));
    return u;
}
union F4 { float4 v; unsigned long long u[2]; };

// ==============================================================================
// GEMM tile core (unchanged): C[32, 64-tile] = X @ W^T over K chunk range.
// ==============================================================================
__device__ __forceinline__ void gemm_tile(
    const float* __restrict__ X, const float* __restrict__ W,
    float* __restrict__ out, int tile, int c_begin, int c_end)
{
    __shared__ float Xs[32 * 68];
    __shared__ float Ws[64 * 68];

    const int tid = threadIdx.x;
    const int tx = tid & 31;
    const int ty = tid >> 5;

    unsigned long long acc[4][2];
#pragma unroll
    for (int i = 0; i < 4; i++) { acc[i][0] = 0ull; acc[i][1] = 0ull; }

    float4 px[2], pw[4];
    {
        const int k0 = c_begin * 64;
#pragma unroll
        for (int i = 0; i < 2; i++) {
            int fid = i * 256 + tid; int m = fid >> 4, c4 = fid & 15;
            px[i] = *(const float4*)(X + (size_t)m * DMODEL + k0 + c4 * 4);
        }
#pragma unroll
        for (int i = 0; i < 4; i++) {
            int fid = i * 256 + tid; int n = fid >> 4, c4 = fid & 15;
            pw[i] = *(const float4*)(W + (size_t)(tile * 64 + n) * DMODEL + k0 + c4 * 4);
        }
    }

    for (int c = c_begin; c < c_end; ++c) {
#pragma unroll
        for (int i = 0; i < 2; i++) {
            int fid = i * 256 + tid; int m = fid >> 4, c4 = fid & 15;
            *(float4*)(Xs + m * 68 + c4 * 4) = px[i];
        }
#pragma unroll
        for (int i = 0; i < 4; i++) {
            int fid = i * 256 + tid; int n = fid >> 4, c4 = fid & 15;
            *(float4*)(Ws + n * 68 + c4 * 4) = pw[i];
        }
        __syncthreads();

        if (c + 1 < c_end) {
            const int k0 = (c + 1) * 64;
#pragma unroll
            for (int i = 0; i < 2; i++) {
                int fid = i * 256 + tid; int m = fid >> 4, c4 = fid & 15;
                px[i] = *(const float4*)(X + (size_t)m * DMODEL + k0 + c4 * 4);
            }
#pragma unroll
            for (int i = 0; i < 4; i++) {
                int fid = i * 256 + tid; int n = fid >> 4, c4 = fid & 15;
                pw[i] = *(const float4*)(W + (size_t)(tile * 64 + n) * DMODEL + k0 + c4 * 4);
            }
        }

#pragma unroll
        for (int kk = 0; kk < 64; kk += 8) {
            F4 w00, w01, w10, w11;
            w00.v = *(const float4*)(Ws + tx * 68 + kk);
            w01.v = *(const float4*)(Ws + tx * 68 + kk + 4);
            w10.v = *(const float4*)(Ws + (tx + 32) * 68 + kk);
            w11.v = *(const float4*)(Ws + (tx + 32) * 68 + kk + 4);
#pragma unroll
            for (int i = 0; i < 4; i++) {
                F4 xa, xb;
                xa.v = *(const float4*)(Xs + (ty * 4 + i) * 68 + kk);
                xb.v = *(const float4*)(Xs + (ty * 4 + i) * 68 + kk + 4);
                ffma2(acc[i][0], xa.u[0], w00.u[0]);
                ffma2(acc[i][0], xa.u[1], w00.u[1]);
                ffma2(acc[i][0], xb.u[0], w01.u[0]);
                ffma2(acc[i][0], xb.u[1], w01.u[1]);
                ffma2(acc[i][1], xa.u[0], w10.u[0]);
                ffma2(acc[i][1], xa.u[1], w10.u[1]);
                ffma2(acc[i][1], xb.u[0], w11.u[0]);
                ffma2(acc[i][1], xb.u[1], w11.u[1]);
            }
        }
        __syncthreads();
    }

#pragma unroll
    for (int i = 0; i < 4; i++) {
#pragma unroll
        for (int j = 0; j < 2; j++) {
            float2 h2 = unpack2(acc[i][j]);
            out[(size_t)(ty * 4 + i) * DMODEL + tile * 64 + tx + j * 32] = h2.x + h2.y;
        }
    }
}

__global__ void __launch_bounds__(256) qkv_gemm_kernel(
    const float* __restrict__ x,
    const float* __restrict__ wq, const float* __restrict__ wk,
    const float* __restrict__ wv)
{
    const int tile = blockIdx.x & 31;
    const int ks   = (blockIdx.x >> 5) & 3;
    const int g    = blockIdx.x >> 7;
    const float* W = (g == 0) ? wq : (g == 1 ? wk : wv);
    gemm_tile(x, W, g_qkvp[g][ks], tile, ks * 8, ks * 8 + 8);
}

__global__ void __launch_bounds__(256) wo_gemm_kernel(const float* __restrict__ wo)
{
    const int ks = blockIdx.x >> 5;
    const int tile = blockIdx.x & 31;
    gemm_tile(g_attn, wo, g_part[ks], tile, ks * 4, ks * 4 + 4);
}

__global__ void __launch_bounds__(256) combine_kernel(float* __restrict__ out)
{
    const int i = blockIdx.x * 256 + threadIdx.x;
    float r = 0.f;
#pragma unroll
    for (int ks = 0; ks < WO_SPLIT; ks++) r += g_part[ks][i];
    out[i] = r;
}

// ==============================================================================
// Attention v6: fully fused single-pass QK -> exp -> AV (no-max softmax).
//   block = (b, h, split of 512 cache keys), 256 threads, 8 warps.
//   Warp owns 64 keys; 8-lane group owns key (round*4+g); lane owns d-segment s.
//   Per round: load K row segment + V row segment, dot vs register q,
//   butterfly reduce, exp, FMA V into per-lane f32x2 accumulators.
//   K and V streamed together in ONE pass — no score smem, no second phase.
// ==============================================================================
__global__ void __launch_bounds__(256, 2) attn_kernel(
    const float* __restrict__ ck, const float* __restrict__ cv,
    const float* __restrict__ fc, const float* __restrict__ fs)
{
    __shared__ float qs[4 * 68];
    __shared__ float kxs[4 * 68];
    __shared__ float vxs[4 * 68];
    __shared__ float avred[8 * 256];
    __shared__ float red[40];
    __shared__ float scnew[16];     // [j][q] new-token exp scores

    const int bh    = blockIdx.x >> 3;
    const int split = blockIdx.x & 7;
    const int b = bh >> 5;
    const int h = bh & 31;
    const int tid = threadIdx.x;
    const int kbase = split * KPB;
    const int wid = tid >> 5, lane = tid & 31;

    // ---------------- prologue: combine qkv partials + RoPE -----------------
    if (tid < 128) {
        const int s = tid >> 5, p = tid & 31;
        const size_t off = (size_t)(b * SEQ + s) * DMODEL + h * HDIM + 2 * p;
        float2 e = *(const float2*)(&g_qkvp[0][0][off]);
#pragma unroll
        for (int ks = 1; ks < QKV_SPLIT; ks++) {
            const float2 t = *(const float2*)(&g_qkvp[0][ks][off]);
            e.x += t.x; e.y += t.y;
        }
        const float c  = fc[s * 32 + p];
        const float sn = fs[s * 32 + p];
        qs[s * 68 + 2 * p]     = (e.x * c - e.y * sn) * 0.125f;
        qs[s * 68 + 2 * p + 1] = (e.x * sn + e.y * c) * 0.125f;
    } else if (split == SPLIT - 1) {
        const int t2 = tid - 128;
        const int s = t2 >> 5, p = t2 & 31;
        const size_t off = (size_t)(b * SEQ + s) * DMODEL + h * HDIM + 2 * p;
        float2 e = *(const float2*)(&g_qkvp[1][0][off]);
#pragma unroll
        for (int ks = 1; ks < QKV_SPLIT; ks++) {
            const float2 t = *(const float2*)(&g_qkvp[1][ks][off]);
            e.x += t.x; e.y += t.y;
        }
        const float c  = fc[s * 32 + p];
        const float sn = fs[s * 32 + p];
        kxs[s * 68 + 2 * p]     = e.x * c - e.y * sn;
        kxs[s * 68 + 2 * p + 1] = e.x * sn + e.y * c;
        float2 v = *(const float2*)(&g_qkvp[2][0][off]);
#pragma unroll
        for (int ks = 1; ks < QKV_SPLIT; ks++) {
            const float2 t = *(const float2*)(&g_qkvp[2][ks][off]);
            v.x += t.x; v.y += t.y;
        }
        vxs[s * 68 + 2 * p]     = v.x;
        vxs[s * 68 + 2 * p + 1] = v.y;
    }
    __syncthreads();

    const int g = lane >> 3;        // key within 4-key round
    const int s = lane & 7;         // 32B d-segment within row

    // register-resident q (pre-scaled)
    F4 qr[4][2];
#pragma unroll
    for (int qi = 0; qi < 4; qi++) {
        qr[qi][0].v = *(const float4*)(qs + qi * 68 + s * 4);
        qr[qi][1].v = *(const float4*)(qs + qi * 68 + s * 4 + 32);
    }

    const size_t rs = NHEAD * HDIM;  // 2048 floats between cache rows
    const size_t rowoff = ((size_t)b * CACHE * NHEAD + h) * HDIM
                        + (size_t)(kbase + wid * 64 + g) * rs + s * 4;
    const float* kp = ck + rowoff;
    const float* vp = cv + rowoff;

    unsigned long long acc[4][4];
#pragma unroll
    for (int q = 0; q < 4; q++)
#pragma unroll
        for (int j = 0; j < 4; j++) acc[q][j] = 0ull;
    float ssum = 0.f;

    // double-buffered fused mainloop: 16 rounds x 4 keys
    F4 kA[2][2], vA[2][2];
    kA[0][0].v = *(const float4*)(kp);
    kA[0][1].v = *(const float4*)(kp + 32);
    vA[0][0].v = *(const float4*)(vp);
    vA[0][1].v = *(const float4*)(vp + 32);

#pragma unroll
    for (int r = 0; r < 16; r++) {
        const int cur = r & 1, nxt = cur ^ 1;
        if (r < 15) {
            const float* kn = kp + (size_t)(r + 1) * 4 * rs;
            const float* vn = vp + (size_t)(r + 1) * 4 * rs;
            kA[nxt][0].v = *(const float4*)(kn);
            kA[nxt][1].v = *(const float4*)(kn + 32);
            vA[nxt][0].v = *(const float4*)(vn);
            vA[nxt][1].v = *(const float4*)(vn + 32);
        }

        float p0, p1, p2, p3;
        {
            unsigned long long a = 0ull;
            ffma2(a, kA[cur][0].u[0], qr[0][0].u[0]); ffma2(a, kA[cur][0].u[1], qr[0][0].u[1]);
            ffma2(a, kA[cur][1].u[0], qr[0][1].u[0]); ffma2(a, kA[cur][1].u[1], qr[0][1].u[1]);
            const float2 t = unpack2(a); p0 = t.x + t.y;
        }
        {
            unsigned long long a = 0ull;
            ffma2(a, kA[cur][0].u[0], qr[1][0].u[0]); ffma2(a, kA[cur][0].u[1], qr[1][0].u[1]);
            ffma2(a, kA[cur][1].u[0], qr[1][1].u[0]); ffma2(a, kA[cur][1].u[1], qr[1][1].u[1]);
            const float2 t = unpack2(a); p1 = t.x + t.y;
        }
        {
            unsigned long long a = 0ull;
            ffma2(a, kA[cur][0].u[0], qr[2][0].u[0]); ffma2(a, kA[cur][0].u[1], qr[2][0].u[1]);
            ffma2(a, kA[cur][1].u[0], qr[2][1].u[0]); ffma2(a, kA[cur][1].u[1], qr[2][1].u[1]);
            const float2 t = unpack2(a); p2 = t.x + t.y;
        }
        {
            unsigned long long a = 0ull;
            ffma2(a, kA[cur][0].u[0], qr[3][0].u[0]); ffma2(a, kA[cur][0].u[1], qr[3][0].u[1]);
            ffma2(a, kA[cur][1].u[0], qr[3][1].u[0]); ffma2(a, kA[cur][1].u[1], qr[3][1].u[1]);
            const float2 t = unpack2(a); p3 = t.x + t.y;
        }
#pragma unroll
        for (int o = 1; o <= 4; o <<= 1) {
            p0 += __shfl_xor_sync(0xffffffffu, p0, o);
            p1 += __shfl_xor_sync(0xffffffffu, p1, o);
            p2 += __shfl_xor_sync(0xffffffffu, p2, o);
            p3 += __shfl_xor_sync(0xffffffffu, p3, o);
        }
        const float e0 = __expf(p0);
        const float e1 = __expf(p1);
        const float e2 = __expf(p2);
        const float e3 = __expf(p3);
        {   // lane s (<4) accumulates exp-sum for q = s
            const float pa = (s & 1) ? e1 : e0;
            const float pb = (s & 1) ? e3 : e2;
            if (s < 4) ssum += (s & 2) ? pb : pa;
        }
        // fused AV: FMA this key's V row into accumulators
        {
            const unsigned long long ee0 = pack2(e0, e0);
            const unsigned long long ee1 = pack2(e1, e1);
            const unsigned long long ee2 = pack2(e2, e2);
            const unsigned long long ee3 = pack2(e3, e3);
            ffma2(acc[0][0], vA[cur][0].u[0], ee0); ffma2(acc[0][1], vA[cur][0].u[1], ee0);
            ffma2(acc[0][2], vA[cur][1].u[0], ee0); ffma2(acc[0][3], vA[cur][1].u[1], ee0);
            ffma2(acc[1][0], vA[cur][0].u[0], ee1); ffma2(acc[1][1], vA[cur][0].u[1], ee1);
            ffma2(acc[1][2], vA[cur][1].u[0], ee1); ffma2(acc[1][3], vA[cur][1].u[1], ee1);
            ffma2(acc[2][0], vA[cur][0].u[0], ee2); ffma2(acc[2][1], vA[cur][0].u[1], ee2);
            ffma2(acc[2][2], vA[cur][1].u[0], ee2); ffma2(acc[2][3], vA[cur][1].u[1], ee2);
            ffma2(acc[3][0], vA[cur][0].u[0], ee3); ffma2(acc[3][1], vA[cur][0].u[1], ee3);
            ffma2(acc[3][2], vA[cur][1].u[0], ee3); ffma2(acc[3][3], vA[cur][1].u[1], ee3);
        }
    }

    // reduce accumulators across the 4 groups (same s, different g)
#pragma unroll
    for (int q = 0; q < 4; q++) {
        float o0 = unpack2(acc[q][0]).x, o1 = unpack2(acc[q][0]).y;
        float o2 = unpack2(acc[q][1]).x, o3 = unpack2(acc[q][1]).y;
        float o4 = unpack2(acc[q][2]).x, o5 = unpack2(acc[q][2]).y;
        float o6 = unpack2(acc[q][3]).x, o7 = unpack2(acc[q][3]).y;
#pragma unroll
        for (int o = 8; o <= 16; o <<= 1) {
            o0 += __shfl_xor_sync(0xffffffffu, o0, o);
            o1 += __shfl_xor_sync(0xffffffffu, o1, o);
            o2 += __shfl_xor_sync(0xffffffffu, o2, o);
            o3 += __shfl_xor_sync(0xffffffffu, o3, o);
            o4 += __shfl_xor_sync(0xffffffffu, o4, o);
            o5 += __shfl_xor_sync(0xffffffffu, o5, o);
            o6 += __shfl_xor_sync(0xffffffffu, o6, o);
            o7 += __shfl_xor_sync(0xffffffffu, o7, o);
        }
        if (g == 0) {
            *(float4*)(avred + wid * 256 + q * 64 + s * 4) =
                make_float4(o0, o1, o2, o3);
            *(float4*)(avred + wid * 256 + q * 64 + 32 + s * 4) =
                make_float4(o4, o5, o6, o7);
        }
    }
    // exp-sum reduce across groups
    ssum += __shfl_xor_sync(0xffffffffu, ssum, 8);
    ssum += __shfl_xor_sync(0xffffffffu, ssum, 16);
    if (lane < 4) red[wid * 4 + lane] = ssum;

    // new-token exp-scores (split 7) / zeros otherwise
    if (split == SPLIT - 1) {
        if (tid < 16) {
            const int q = tid >> 2, j = tid & 3;
            float a = 0.f;
#pragma unroll
            for (int d = 0; d < HDIM; d++) a += qs[q * 68 + d] * kxs[j * 68 + d];
            scnew[j * 4 + q] = (j > q) ? 0.f : __expf(a);
        }
    } else if (tid < 16) {
        scnew[tid] = 0.f;
    }
    __syncthreads();

    if (tid < 4) {
        float t = 0.f;
#pragma unroll
        for (int w = 0; w < 8; w++) t += red[w * 4 + tid];
#pragma unroll
        for (int j = 0; j < SEQ; j++) t += scnew[j * 4 + tid];
        red[32 + tid] = t;
    }
    __syncthreads();

    // output: unnormalized partial + s
    {
        const int q = tid >> 6, d = tid & 63;
        float r = 0.f;
#pragma unroll
        for (int w = 0; w < 8; w++) r += avred[w * 256 + q * 64 + d];
        if (split == SPLIT - 1) {
#pragma unroll
            for (int j = 0; j < SEQ; j++)
                r += scnew[j * 4 + q] * vxs[j * 68 + d];
        }
        const int base = (bh * SPLIT + split) * SEQ + q;
        g_po[(size_t)base * HDIM + d] = r;
        if (d == 0) g_s[base] = red[32 + q];
    }
}

// merge the 8 split partials per (b, h): pure sum
__global__ void __launch_bounds__(256) attn_combine_kernel()
{
    const int bh = blockIdx.x;
    const int tid = threadIdx.x;
    const int q = tid >> 6, d = tid & 63;

    float num = 0.f, den = 0.f;
#pragma unroll
    for (int i = 0; i < SPLIT; i++) {
        const int base = (bh * SPLIT + i) * SEQ + q;
        num += g_po[(size_t)base * HDIM + d];
        den += g_s[base];
    }
    const int b = bh >> 5, h = bh & 31;
    g_attn[(size_t)(b * SEQ + q) * DMODEL + h * HDIM + d] = num / den;
}

// ==============================================================================
extern "C" void kernel_launch(void* const* d_in, const int* in_sizes, int n_in,
                              void* d_out, int out_size)
{
    const float* x  = (const float*)d_in[0];
    const float* fc = (const float*)d_in[1];
    const float* fs = (const float*)d_in[2];
    const float* ck = (const float*)d_in[4];
    const float* cv = (const float*)d_in[5];
    const float* wq = (const float*)d_in[6];
    const float* wk = (const float*)d_in[7];
    const float* wv = (const float*)d_in[8];
    const float* wo = (const float*)d_in[9];
    float* out = (float*)d_out;

    qkv_gemm_kernel<<<3 * QKV_SPLIT * 32, 256>>>(x, wq, wk, wv);
    attn_kernel<<<BATCH * NHEAD * SPLIT, 256>>>(ck, cv, fc, fs);
    attn_combine_kernel<<<BATCH * NHEAD, 256>>>();
    wo_gemm_kernel<<<WO_SPLIT * 32, 256>>>(wo);
    combine_kernel<<<MROWS * DMODEL / 256, 256>>>(out);
}